// round 12
// baseline (speedup 1.0000x reference)
#include <cuda_runtime.h>
#include <cuda_bf16.h>
#include <math.h>

// Shapes (fixed by the problem)
#define NB 4
#define NH 16
#define NS 1024
#define ND 1024
#define HD 64
#define NK2 512   // 2 * BUCKETS
#define SPAN 256  // BUCKETS

// ---------------- scratch (device globals; no allocs allowed) ----------------
__device__ float g_re[NK2 * ND];
__device__ float g_q[(size_t)NB * NH * NS * HD];
__device__ float g_k[(size_t)NB * NH * NS * HD];
__device__ float g_v[(size_t)NB * NH * NS * HD];
__device__ float g_posk[NH * NK2 * HD];
__device__ float g_posq[NH * NK2 * HD];
__device__ __nv_bfloat16 g_c2p[(size_t)NB * NH * NS * NK2];  // pre-scaled by inv128/inv192
__device__ __nv_bfloat16 g_p2c[(size_t)NB * NH * NS * NK2];  // pre-scaled by inv128/inv192
__device__ float g_ctx[(size_t)NB * NS * ND];
__device__ int2  g_idx[2 * NS - 1];   // (idx1, idx2) per delta

// ---------------- helpers ----------------
__device__ __forceinline__ float f2tf(float x) {
    unsigned u;
    asm("cvt.rna.tf32.f32 %0, %1;" : "=r"(u) : "f"(x));
    return __uint_as_float(u);
}

__device__ __forceinline__ void mma_tf32(float* c, const float* a, const float* b) {
    asm volatile("mma.sync.aligned.m16n8k8.row.col.f32.tf32.tf32.f32 "
                 "{%0,%1,%2,%3}, {%4,%5,%6,%7}, {%8,%9}, {%0,%1,%2,%3};\n"
                 : "+f"(c[0]), "+f"(c[1]), "+f"(c[2]), "+f"(c[3])
                 : "r"(__float_as_uint(a[0])), "r"(__float_as_uint(a[1])),
                   "r"(__float_as_uint(a[2])), "r"(__float_as_uint(a[3])),
                   "r"(__float_as_uint(b[0])), "r"(__float_as_uint(b[1])));
}

__device__ __forceinline__ void cp16(float* dst, const float* src) {
    unsigned s = (unsigned)__cvta_generic_to_shared(dst);
    asm volatile("cp.async.cg.shared.global [%0], [%1], 16;" :: "r"(s), "l"(src));
}
__device__ __forceinline__ void cp_commit() { asm volatile("cp.async.commit_group;"); }
__device__ __forceinline__ void cp_wait0()  { asm volatile("cp.async.wait_group 0;"); }
__device__ __forceinline__ void cp_wait1()  { asm volatile("cp.async.wait_group 1;"); }
__device__ __forceinline__ void cp_wait2()  { asm volatile("cp.async.wait_group 2;"); }
__device__ __forceinline__ void cp_wait3()  { asm volatile("cp.async.wait_group 3;"); }

// ---------------- bucket + index table (matches jax f32 semantics) -----------
__device__ __forceinline__ int bucketf(int rel) {
    const float mid = 128.0f;
    float signf = (rel > 0) ? 1.0f : (rel < 0 ? -1.0f : 0.0f);
    float abs_pos = (rel < 128 && rel > -128) ? 127.0f : fabsf((float)rel);
    float bucket;
    if (abs_pos <= mid) {
        bucket = (float)rel;
    } else {
        const float LOGC = 1.3843393289f;  // log(511/128) as f32
        float log_pos = ceilf(logf(abs_pos / mid) / LOGC * 127.0f) + mid;
        bucket = log_pos * signf;
    }
    return (int)bucket;
}

__global__ void build_idx_kernel(int2* idx) {
    int i = blockIdx.x * blockDim.x + threadIdx.x;
    if (i >= 2 * NS - 1) return;
    int rel = i - (NS - 1);          // delta = i - j
    int b1 = bucketf(rel);
    int b2 = bucketf(-rel);
    int2 v;
    v.x = min(max(b1 + SPAN, 0), 2 * SPAN - 1);
    v.y = min(max(SPAN - b2, 0), 2 * SPAN - 1);
    idx[i] = v;
}

// ---------------- LayerNorm for rel_emb [512,1024] ----------------
__global__ void ln_kernel(const float* __restrict__ x, const float* __restrict__ g,
                          const float* __restrict__ b, float* __restrict__ y) {
    int row = blockIdx.x;
    const float* xr = x + (size_t)row * ND;
    __shared__ float red[256];
    int tid = threadIdx.x;

    float s = 0.f;
    for (int i = tid; i < ND; i += 256) s += xr[i];
    red[tid] = s; __syncthreads();
    for (int o = 128; o > 0; o >>= 1) { if (tid < o) red[tid] += red[tid + o]; __syncthreads(); }
    float mu = red[0] * (1.0f / ND);
    __syncthreads();

    float v = 0.f;
    for (int i = tid; i < ND; i += 256) { float d = xr[i] - mu; v += d * d; }
    red[tid] = v; __syncthreads();
    for (int o = 128; o > 0; o >>= 1) { if (tid < o) red[tid] += red[tid + o]; __syncthreads(); }
    float var = red[0] * (1.0f / ND);
    float inv = 1.0f / sqrtf(var + 1e-5f);

    for (int i = tid; i < ND; i += 256)
        y[(size_t)row * ND + i] = (xr[i] - mu) * inv * g[i] + b[i];
}

// ============================================================================
// mm_jobs_tf32: up to 5 independent GEMMs C = A[M,1024] @ W[1024,1024] + bias
// (round-7 version; unchanged)
// ============================================================================
struct MMJob {
    const float* A; const float* W; const float* bias; float* C;
    int M; int splitR;
};
struct MMJobs { MMJob j[5]; };

__global__ __launch_bounds__(256, 2) void mm_jobs_tf32(MMJobs jobs)
{
    __shared__ float As[2][128][20];
    __shared__ float Bs[2][16][136];

    const MMJob jb = jobs.j[blockIdx.z];
    if (blockIdx.y * 128 >= jb.M) return;
    const float* A = jb.A; const float* W = jb.W;
    const float* bias = jb.bias; float* C = jb.C;
    const int splitR = jb.splitR;

    const int t = threadIdx.x, l = t & 31, w = t >> 5;
    const int gm = l >> 2, kq = l & 3;
    const int warpM = (w >> 1) * 32, warpN = (w & 1) * 64;
    const int rowBase = blockIdx.y * 128, colBase = blockIdx.x * 128;

    float acc[2][8][4];
#pragma unroll
    for (int i = 0; i < 2; ++i)
#pragma unroll
        for (int j = 0; j < 8; ++j)
#pragma unroll
            for (int e = 0; e < 4; ++e) acc[i][j][e] = 0.f;

    const int ar = t >> 1, ac = (t & 1) * 8;
    const int bk = t >> 4, bc = (t & 15) * 8;

    cp16(&As[0][ar][ac],     A + (size_t)(rowBase + ar) * ND + ac);
    cp16(&As[0][ar][ac + 4], A + (size_t)(rowBase + ar) * ND + ac + 4);
    cp16(&Bs[0][bk][bc],     W + (size_t)bk * ND + colBase + bc);
    cp16(&Bs[0][bk][bc + 4], W + (size_t)bk * ND + colBase + bc + 4);
    cp_commit();

    for (int c = 0; c < ND / 16; ++c) {
        if (c + 1 < ND / 16) {
            int k0 = (c + 1) * 16, s = (c + 1) & 1;
            cp16(&As[s][ar][ac],     A + (size_t)(rowBase + ar) * ND + k0 + ac);
            cp16(&As[s][ar][ac + 4], A + (size_t)(rowBase + ar) * ND + k0 + ac + 4);
            cp16(&Bs[s][bk][bc],     W + (size_t)(k0 + bk) * ND + colBase + bc);
            cp16(&Bs[s][bk][bc + 4], W + (size_t)(k0 + bk) * ND + colBase + bc + 4);
            cp_commit();
            cp_wait1();
        } else {
            cp_wait0();
        }
        __syncthreads();

        const int s = c & 1;
#pragma unroll
        for (int ks = 0; ks < 2; ++ks) {
            const int k = ks * 8;
            float a[2][4], b[8][2];
#pragma unroll
            for (int mt = 0; mt < 2; ++mt) {
                int m = warpM + mt * 16 + gm;
                a[mt][0] = f2tf(As[s][m][k + kq]);
                a[mt][1] = f2tf(As[s][m + 8][k + kq]);
                a[mt][2] = f2tf(As[s][m][k + kq + 4]);
                a[mt][3] = f2tf(As[s][m + 8][k + kq + 4]);
            }
#pragma unroll
            for (int nt = 0; nt < 8; ++nt) {
                int n = warpN + nt * 8 + gm;
                b[nt][0] = f2tf(Bs[s][k + kq][n]);
                b[nt][1] = f2tf(Bs[s][k + kq + 4][n]);
            }
#pragma unroll
            for (int mt = 0; mt < 2; ++mt)
#pragma unroll
                for (int nt = 0; nt < 8; ++nt)
                    mma_tf32(acc[mt][nt], a[mt], b[nt]);
        }
        __syncthreads();
    }

#pragma unroll
    for (int mt = 0; mt < 2; ++mt) {
#pragma unroll
        for (int nt = 0; nt < 8; ++nt) {
            int r0 = rowBase + warpM + mt * 16 + gm;
            int c0 = colBase + warpN + nt * 8 + kq * 2;
#pragma unroll
            for (int half = 0; half < 2; ++half) {
                int r = r0 + half * 8;
                float v0 = acc[mt][nt][half * 2 + 0] + bias[c0];
                float v1 = acc[mt][nt][half * 2 + 1] + bias[c0 + 1];
                if (splitR == 0) {
                    *(float2*)&C[(size_t)r * ND + c0] = make_float2(v0, v1);
                } else {
                    v0 = f2tf(v0); v1 = f2tf(v1);
                    int h = c0 >> 6, d = c0 & 63;
                    int bb = r / splitR, rr = r - bb * splitR;
                    *(float2*)&C[(((size_t)bb * NH + h) * splitR + rr) * HD + d] =
                        make_float2(v0, v1);
                }
            }
        }
    }
}

// ============================================================================
// nt64_pair_tf32: c2p and p2c in one launch.
// Progressive 4-chunk load: one thread per row, 4 commit groups of 16 cols,
// wait_group 3/2/1/0 per chunk -> only first-chunk latency exposed.
// Dynamic smem 73728 B, 2 CTAs/SM. bf16 out pre-scaled by inv128/inv192.
// ============================================================================
__global__ __launch_bounds__(256, 2) void nt64_pair_tf32(
    const float* __restrict__ q, const float* __restrict__ posk,
    const float* __restrict__ kk, const float* __restrict__ posq,
    __nv_bfloat16* __restrict__ c2p, __nv_bfloat16* __restrict__ p2c)
{
    extern __shared__ float sm[];
    float (*Asm)[72] = (float(*)[72])sm;              // [128][72]
    float (*Bsm)[72] = (float(*)[72])(sm + 128 * 72); // [128][72]

    const int t = threadIdx.x, l = t & 31, w = t >> 5;
    const int gm = l >> 2, kq = l & 3;
    const int warpM = (w >> 1) * 32, warpN = (w & 1) * 64;
    const int zz = blockIdx.z;
    const int batch = zz & 63;
    const int iBase = blockIdx.y * 128, jBase = blockIdx.x * 128;

    const float* Ab = ((zz < 64) ? q : kk) + (size_t)batch * NS * HD;
    const float* Bb = ((zz < 64) ? posk : posq) + (size_t)(batch & 15) * NK2 * HD;
    __nv_bfloat16* Cb = ((zz < 64) ? c2p : p2c) + (size_t)batch * NS * NK2;

    // one thread per row: t<128 -> A row t; else B row t-128
    const float* rowp = (t < 128) ? (Ab + (size_t)(iBase + t) * HD)
                                  : (Bb + (size_t)(jBase + (t - 128)) * HD);
    float* dstrow = (t < 128) ? Asm[t] : Bsm[t - 128];

#pragma unroll
    for (int c = 0; c < 4; ++c) {
        cp16(&dstrow[c * 16],      rowp + c * 16);
        cp16(&dstrow[c * 16 + 4],  rowp + c * 16 + 4);
        cp16(&dstrow[c * 16 + 8],  rowp + c * 16 + 8);
        cp16(&dstrow[c * 16 + 12], rowp + c * 16 + 12);
        cp_commit();
    }

    float acc[2][8][4];
#pragma unroll
    for (int i = 0; i < 2; ++i)
#pragma unroll
        for (int j = 0; j < 8; ++j)
#pragma unroll
            for (int e = 0; e < 4; ++e) acc[i][j][e] = 0.f;

#pragma unroll
    for (int c = 0; c < 4; ++c) {
        if (c == 0) cp_wait3();
        else if (c == 1) cp_wait2();
        else if (c == 2) cp_wait1();
        else cp_wait0();
        __syncthreads();

#pragma unroll
        for (int ks = 0; ks < 2; ++ks) {
            const int k = c * 16 + ks * 8;
            float a[2][4], b[8][2];
#pragma unroll
            for (int mt = 0; mt < 2; ++mt) {
                int m = warpM + mt * 16 + gm;
                a[mt][0] = Asm[m][k + kq];
                a[mt][1] = Asm[m + 8][k + kq];
                a[mt][2] = Asm[m][k + kq + 4];
                a[mt][3] = Asm[m + 8][k + kq + 4];
            }
#pragma unroll
            for (int nt = 0; nt < 8; ++nt) {
                int n = warpN + nt * 8 + gm;
                b[nt][0] = Bsm[n][k + kq];
                b[nt][1] = Bsm[n][k + kq + 4];
            }
#pragma unroll
            for (int mt = 0; mt < 2; ++mt)
#pragma unroll
                for (int nt = 0; nt < 8; ++nt)
                    mma_tf32(acc[mt][nt], a[mt], b[nt]);
        }
    }

    // store pre-scaled by inv128/inv192 = sqrt(1.5): flash multiplies everything by inv192
    const float sstore = 1.2247448713915890f;
#pragma unroll
    for (int mt = 0; mt < 2; ++mt)
#pragma unroll
        for (int nt = 0; nt < 8; ++nt) {
            int r0 = iBase + warpM + mt * 16 + gm;
            int c0 = jBase + warpN + nt * 8 + kq * 2;
#pragma unroll
            for (int half = 0; half < 2; ++half) {
                __nv_bfloat162 pk;
                pk.x = __float2bfloat16(acc[mt][nt][half * 2 + 0] * sstore);
                pk.y = __float2bfloat16(acc[mt][nt][half * 2 + 1] * sstore);
                *(__nv_bfloat162*)&Cb[(size_t)(r0 + half * 8) * NK2 + c0] = pk;
            }
        }
}

// ============================================================================
// flash_tf32: fused scores(QK^T + rel-pos bias) -> online softmax -> PV.
// Bias gathers now INITIALIZE the S accumulator before the K-tile wait, so
// the scattered loads overlap the cp.async wait + MMA issue. The single
// inv192 scale is folded into the exp argument (softmax state in raw units).
// ============================================================================
__global__ __launch_bounds__(256, 1) void flash_tf32(
    const float* __restrict__ q, const float* __restrict__ k,
    const float* __restrict__ v,
    const __nv_bfloat16* __restrict__ c2p, const __nv_bfloat16* __restrict__ p2c,
    const int2* __restrict__ idxt, float* __restrict__ ctx)
{
    extern __shared__ float smf[];
    float (*X0)[72] = (float(*)[72])smf;
    float (*X1)[72] = (float(*)[72])(smf + 128 * 72);

    const int t = threadIdx.x, l = t & 31, w = t >> 5;
    const int gm = l >> 2, kq = l & 3;
    const int warpM = w * 16;
    const int z = blockIdx.y;
    const int bz = z >> 4, h = z & 15;
    const int iBase = blockIdx.x * 128;

    const float* Qb = q + (size_t)z * NS * HD;
    const float* Kb = k + (size_t)z * NS * HD;
    const float* Vb = v + (size_t)z * NS * HD;
    const __nv_bfloat16* c2pr = c2p + (size_t)z * NS * NK2;
    const __nv_bfloat16* p2cr = p2c + (size_t)z * NS * NK2;

    const int sr = t >> 1, cb = (t & 1) * 32;
    const int i0 = iBase + warpM + gm;
    const int i1 = i0 + 8;

    // ---- load Q tile -> X0, extract fragments ----
#pragma unroll
    for (int i = 0; i < 8; ++i)
        cp16(&X0[sr][cb + i * 4], Qb + (size_t)(iBase + sr) * HD + cb + i * 4);
    cp_commit(); cp_wait0();
    __syncthreads();

    float aq[8][4];
    {
        int m = warpM + gm;
#pragma unroll
        for (int ks = 0; ks < 8; ++ks) {
            int kk = ks * 8;
            aq[ks][0] = X0[m][kk + kq];
            aq[ks][1] = X0[m + 8][kk + kq];
            aq[ks][2] = X0[m][kk + kq + 4];
            aq[ks][3] = X0[m + 8][kk + kq + 4];
        }
    }
    __syncthreads();

    // prefetch K(0) -> X0
#pragma unroll
    for (int i = 0; i < 8; ++i)
        cp16(&X0[sr][cb + i * 4], Kb + (size_t)sr * HD + cb + i * 4);
    cp_commit();   // pending: [K0]

    float m0 = -INFINITY, m1 = -INFINITY, l0 = 0.f, l1 = 0.f;   // raw (unscaled) units
    float o[8][4];
#pragma unroll
    for (int i = 0; i < 8; ++i)
#pragma unroll
        for (int e = 0; e < 4; ++e) o[i][e] = 0.f;

    const float inv192 = 0.07216878364870322f;  // 1/sqrt(64*3)
    const int srcA = (l & ~3) | (kq >> 1);
    const int srcB = srcA + 2;
    const bool odd = (kq & 1);

    for (int jt = 0; jt < 8; ++jt) {
        const int jBase = jt * 128;

        // issue V(jt) -> X1
#pragma unroll
        for (int i = 0; i < 8; ++i)
            cp16(&X1[sr][cb + i * 4], Vb + (size_t)(jBase + sr) * HD + cb + i * 4);
        cp_commit();        // pending: [K(jt), V(jt)]

        // ---- bias gathers initialize S (overlap with K(jt) in flight) ----
        float sc[16][4];
#pragma unroll
        for (int nt = 0; nt < 16; ++nt) {
#pragma unroll
            for (int e = 0; e < 4; ++e) {
                int i = (e < 2) ? i0 : i1;
                int j = jBase + nt * 8 + kq * 2 + (e & 1);
                int2 ip = idxt[i - j + (NS - 1)];
                sc[nt][e] = __bfloat162float(c2pr[(size_t)i * NK2 + ip.x])
                          + __bfloat162float(p2cr[(size_t)j * NK2 + ip.y]);
            }
        }

        cp_wait1();         // K(jt) resident
        __syncthreads();

        // ---- S += Q K^T ----
#pragma unroll
        for (int ks = 0; ks < 8; ++ks) {
            const int kk = ks * 8;
#pragma unroll
            for (int nt = 0; nt < 16; ++nt) {
                int n = nt * 8 + gm;
                float b[2];
                b[0] = X0[n][kk + kq];
                b[1] = X0[n][kk + kq + 4];
                mma_tf32(sc[nt], aq[ks], b);
            }
        }
        __syncthreads();

        // prefetch K(jt+1) -> X0 (overlaps softmax)
        if (jt + 1 < 8) {
#pragma unroll
            for (int i = 0; i < 8; ++i)
                cp16(&X0[sr][cb + i * 4],
                     Kb + (size_t)((jt + 1) * 128 + sr) * HD + cb + i * 4);
            cp_commit();
        }

        // ---- online softmax (raw units; inv192 folded into exp args) ----
        float tm0 = -INFINITY, tm1 = -INFINITY;
#pragma unroll
        for (int nt = 0; nt < 16; ++nt) {
            tm0 = fmaxf(tm0, fmaxf(sc[nt][0], sc[nt][1]));
            tm1 = fmaxf(tm1, fmaxf(sc[nt][2], sc[nt][3]));
        }
        tm0 = fmaxf(tm0, __shfl_xor_sync(0xffffffffu, tm0, 1));
        tm0 = fmaxf(tm0, __shfl_xor_sync(0xffffffffu, tm0, 2));
        tm1 = fmaxf(tm1, __shfl_xor_sync(0xffffffffu, tm1, 1));
        tm1 = fmaxf(tm1, __shfl_xor_sync(0xffffffffu, tm1, 2));

        float mn0 = fmaxf(m0, tm0), mn1 = fmaxf(m1, tm1);
        float fac0 = expf((m0 - mn0) * inv192);
        float fac1 = expf((m1 - mn1) * inv192);
        m0 = mn0; m1 = mn1;

        float s0 = 0.f, s1 = 0.f;
#pragma unroll
        for (int nt = 0; nt < 16; ++nt) {
            sc[nt][0] = f2tf(expf((sc[nt][0] - mn0) * inv192));
            sc[nt][1] = f2tf(expf((sc[nt][1] - mn0) * inv192));
            sc[nt][2] = f2tf(expf((sc[nt][2] - mn1) * inv192));
            sc[nt][3] = f2tf(expf((sc[nt][3] - mn1) * inv192));
            s0 += sc[nt][0] + sc[nt][1];
            s1 += sc[nt][2] + sc[nt][3];
        }
        s0 += __shfl_xor_sync(0xffffffffu, s0, 1);
        s0 += __shfl_xor_sync(0xffffffffu, s0, 2);
        s1 += __shfl_xor_sync(0xffffffffu, s1, 1);
        s1 += __shfl_xor_sync(0xffffffffu, s1, 2);
        l0 = l0 * fac0 + s0;
        l1 = l1 * fac1 + s1;

#pragma unroll
        for (int nt = 0; nt < 8; ++nt) {
            o[nt][0] *= fac0; o[nt][1] *= fac0;
            o[nt][2] *= fac1; o[nt][3] *= fac1;
        }

        // ---- wait V(jt), then PV ----
        if (jt + 1 < 8) cp_wait1(); else cp_wait0();
        __syncthreads();

#pragma unroll
        for (int ksg = 0; ksg < 16; ++ksg) {
            float e0 = __shfl_sync(0xffffffffu, sc[ksg][0], srcA);
            float e1 = __shfl_sync(0xffffffffu, sc[ksg][1], srcA);
            float e2 = __shfl_sync(0xffffffffu, sc[ksg][2], srcA);
            float e3 = __shfl_sync(0xffffffffu, sc[ksg][3], srcA);
            float f0 = __shfl_sync(0xffffffffu, sc[ksg][0], srcB);
            float f1 = __shfl_sync(0xffffffffu, sc[ksg][1], srcB);
            float f2 = __shfl_sync(0xffffffffu, sc[ksg][2], srcB);
            float f3 = __shfl_sync(0xffffffffu, sc[ksg][3], srcB);
            float pa[4];
            pa[0] = odd ? e1 : e0;
            pa[1] = odd ? e3 : e2;
            pa[2] = odd ? f1 : f0;
            pa[3] = odd ? f3 : f2;
#pragma unroll
            for (int nt = 0; nt < 8; ++nt) {
                int n = nt * 8 + gm;
                float b[2];
                b[0] = X1[ksg * 8 + kq][n];
                b[1] = X1[ksg * 8 + kq + 4][n];
                mma_tf32(o[nt], pa, b);
            }
        }
        __syncthreads();
    }

    // ---- normalize and store ctx ----
    float r0 = 1.0f / l0, r1 = 1.0f / l1;
#pragma unroll
    for (int nt = 0; nt < 8; ++nt) {
        int c0 = nt * 8 + kq * 2;
        *(float2*)&ctx[((size_t)bz * NS + i0) * ND + h * HD + c0] =
            make_float2(o[nt][0] * r0, o[nt][1] * r0);
        *(float2*)&ctx[((size_t)bz * NS + i1) * ND + h * HD + c0] =
            make_float2(o[nt][2] * r1, o[nt][3] * r1);
    }
}

// ---------------- launch ----------------
extern "C" void kernel_launch(void* const* d_in, const int* in_sizes, int n_in,
                              void* d_out, int out_size) {
    const float* hs    = (const float*)d_in[0];
    const float* Wq    = (const float*)d_in[1];
    const float* bq    = (const float*)d_in[2];
    const float* Wk    = (const float*)d_in[3];
    const float* bk    = (const float*)d_in[4];
    const float* Wv    = (const float*)d_in[5];
    const float* bv    = (const float*)d_in[6];
    const float* Wo    = (const float*)d_in[7];
    const float* bo    = (const float*)d_in[8];
    const float* rel   = (const float*)d_in[9];
    const float* ln_g  = (const float*)d_in[10];
    const float* ln_b  = (const float*)d_in[11];
    const float* Wpk   = (const float*)d_in[12];
    const float* bpk   = (const float*)d_in[13];
    const float* Wpq   = (const float*)d_in[14];
    const float* bpq   = (const float*)d_in[15];
    float* out = (float*)d_out;

    float *p_re, *p_q, *p_k, *p_v, *p_posk, *p_posq, *p_ctx;
    __nv_bfloat16 *p_c2p, *p_p2c;
    int2* p_idx;
    cudaGetSymbolAddress((void**)&p_re, g_re);
    cudaGetSymbolAddress((void**)&p_q, g_q);
    cudaGetSymbolAddress((void**)&p_k, g_k);
    cudaGetSymbolAddress((void**)&p_v, g_v);
    cudaGetSymbolAddress((void**)&p_posk, g_posk);
    cudaGetSymbolAddress((void**)&p_posq, g_posq);
    cudaGetSymbolAddress((void**)&p_c2p, g_c2p);
    cudaGetSymbolAddress((void**)&p_p2c, g_p2c);
    cudaGetSymbolAddress((void**)&p_ctx, g_ctx);
    cudaGetSymbolAddress((void**)&p_idx, g_idx);

    static bool attr_done = false;
    if (!attr_done) {
        cudaFuncSetAttribute(flash_tf32,
                             cudaFuncAttributeMaxDynamicSharedMemorySize, 73728);
        cudaFuncSetAttribute(nt64_pair_tf32,
                             cudaFuncAttributeMaxDynamicSharedMemorySize, 73728);
        attr_done = true;
    }

    build_idx_kernel<<<9, 256>>>(p_idx);
    ln_kernel<<<NK2, 256>>>(rel, ln_g, ln_b, p_re);

    // merged Q/K/V + pos-k/pos-q projections in one launch
    MMJobs jobs;
    jobs.j[0] = { hs,   Wq,  bq,  p_q,    NB * NS, NS  };
    jobs.j[1] = { hs,   Wk,  bk,  p_k,    NB * NS, NS  };
    jobs.j[2] = { hs,   Wv,  bv,  p_v,    NB * NS, NS  };
    jobs.j[3] = { p_re, Wpk, bpk, p_posk, NK2,     NK2 };
    jobs.j[4] = { p_re, Wpq, bpq, p_posq, NK2,     NK2 };
    mm_jobs_tf32<<<dim3(8, 32, 5), 256>>>(jobs);

    // c2p and p2c in one launch (bf16, pre-scaled by inv128/inv192)
    nt64_pair_tf32<<<dim3(4, 8, 128), 256, 73728>>>(p_q, p_posk, p_k, p_posq, p_c2p, p_p2c);

    // fused attention
    flash_tf32<<<dim3(8, 64), 256, 73728>>>(p_q, p_k, p_v, p_c2p, p_p2c, p_idx, p_ctx);

    // out = ctx @ Wo + bo
    MMJobs jo;
    jo.j[0] = { p_ctx, Wo, bo, out, NB * NS, 0 };
    jo.j[1] = jo.j[0]; jo.j[2] = jo.j[0]; jo.j[3] = jo.j[0]; jo.j[4] = jo.j[0];
    mm_jobs_tf32<<<dim3(8, 32, 1), 256>>>(jo);
}

// round 13
// speedup vs baseline: 1.0373x; 1.0373x over previous
#include <cuda_runtime.h>
#include <cuda_bf16.h>
#include <math.h>

// Shapes (fixed by the problem)
#define NB 4
#define NH 16
#define NS 1024
#define ND 1024
#define HD 64
#define NK2 512   // 2 * BUCKETS
#define SPAN 256  // BUCKETS

// ---------------- scratch (device globals; no allocs allowed) ----------------
__device__ float g_re[NK2 * ND];
__device__ float g_q[(size_t)NB * NH * NS * HD];
__device__ float g_k[(size_t)NB * NH * NS * HD];
__device__ float g_v[(size_t)NB * NH * NS * HD];
__device__ float g_posk[NH * NK2 * HD];
__device__ float g_posq[NH * NK2 * HD];
__device__ __nv_bfloat16 g_c2p[(size_t)NB * NH * NS * NK2];  // pre-scaled by inv128/inv192
__device__ __nv_bfloat16 g_p2c[(size_t)NB * NH * NS * NK2];  // pre-scaled by inv128/inv192
__device__ float g_ctx[(size_t)NB * NS * ND];
__device__ int2  g_idx[2 * NS - 1];   // (idx1, idx2) per delta

// ---------------- helpers ----------------
__device__ __forceinline__ float f2tf(float x) {
    unsigned u;
    asm("cvt.rna.tf32.f32 %0, %1;" : "=r"(u) : "f"(x));
    return __uint_as_float(u);
}

__device__ __forceinline__ void mma_tf32(float* c, const float* a, const float* b) {
    asm volatile("mma.sync.aligned.m16n8k8.row.col.f32.tf32.tf32.f32 "
                 "{%0,%1,%2,%3}, {%4,%5,%6,%7}, {%8,%9}, {%0,%1,%2,%3};\n"
                 : "+f"(c[0]), "+f"(c[1]), "+f"(c[2]), "+f"(c[3])
                 : "r"(__float_as_uint(a[0])), "r"(__float_as_uint(a[1])),
                   "r"(__float_as_uint(a[2])), "r"(__float_as_uint(a[3])),
                   "r"(__float_as_uint(b[0])), "r"(__float_as_uint(b[1])));
}

__device__ __forceinline__ void cp16(float* dst, const float* src) {
    unsigned s = (unsigned)__cvta_generic_to_shared(dst);
    asm volatile("cp.async.cg.shared.global [%0], [%1], 16;" :: "r"(s), "l"(src));
}
__device__ __forceinline__ void cp_commit() { asm volatile("cp.async.commit_group;"); }
__device__ __forceinline__ void cp_wait0()  { asm volatile("cp.async.wait_group 0;"); }
__device__ __forceinline__ void cp_wait1()  { asm volatile("cp.async.wait_group 1;"); }

// ---------------- bucket + index table (matches jax f32 semantics) -----------
__device__ __forceinline__ int bucketf(int rel) {
    const float mid = 128.0f;
    float signf = (rel > 0) ? 1.0f : (rel < 0 ? -1.0f : 0.0f);
    float abs_pos = (rel < 128 && rel > -128) ? 127.0f : fabsf((float)rel);
    float bucket;
    if (abs_pos <= mid) {
        bucket = (float)rel;
    } else {
        const float LOGC = 1.3843393289f;  // log(511/128) as f32
        float log_pos = ceilf(logf(abs_pos / mid) / LOGC * 127.0f) + mid;
        bucket = log_pos * signf;
    }
    return (int)bucket;
}

__global__ void build_idx_kernel(int2* idx) {
    int i = blockIdx.x * blockDim.x + threadIdx.x;
    if (i >= 2 * NS - 1) return;
    int rel = i - (NS - 1);          // delta = i - j
    int b1 = bucketf(rel);
    int b2 = bucketf(-rel);
    int2 v;
    v.x = min(max(b1 + SPAN, 0), 2 * SPAN - 1);
    v.y = min(max(SPAN - b2, 0), 2 * SPAN - 1);
    idx[i] = v;
}

// ---------------- LayerNorm for rel_emb [512,1024] ----------------
__global__ void ln_kernel(const float* __restrict__ x, const float* __restrict__ g,
                          const float* __restrict__ b, float* __restrict__ y) {
    int row = blockIdx.x;
    const float* xr = x + (size_t)row * ND;
    __shared__ float red[256];
    int tid = threadIdx.x;

    float s = 0.f;
    for (int i = tid; i < ND; i += 256) s += xr[i];
    red[tid] = s; __syncthreads();
    for (int o = 128; o > 0; o >>= 1) { if (tid < o) red[tid] += red[tid + o]; __syncthreads(); }
    float mu = red[0] * (1.0f / ND);
    __syncthreads();

    float v = 0.f;
    for (int i = tid; i < ND; i += 256) { float d = xr[i] - mu; v += d * d; }
    red[tid] = v; __syncthreads();
    for (int o = 128; o > 0; o >>= 1) { if (tid < o) red[tid] += red[tid + o]; __syncthreads(); }
    float var = red[0] * (1.0f / ND);
    float inv = 1.0f / sqrtf(var + 1e-5f);

    for (int i = tid; i < ND; i += 256)
        y[(size_t)row * ND + i] = (xr[i] - mu) * inv * g[i] + b[i];
}

// ============================================================================
// mm_jobs_tf32: up to 5 independent GEMMs C = A[M,1024] @ W[1024,1024] + bias
// (round-7 version; unchanged)
// ============================================================================
struct MMJob {
    const float* A; const float* W; const float* bias; float* C;
    int M; int splitR;
};
struct MMJobs { MMJob j[5]; };

__global__ __launch_bounds__(256, 2) void mm_jobs_tf32(MMJobs jobs)
{
    __shared__ float As[2][128][20];
    __shared__ float Bs[2][16][136];

    const MMJob jb = jobs.j[blockIdx.z];
    if (blockIdx.y * 128 >= jb.M) return;
    const float* A = jb.A; const float* W = jb.W;
    const float* bias = jb.bias; float* C = jb.C;
    const int splitR = jb.splitR;

    const int t = threadIdx.x, l = t & 31, w = t >> 5;
    const int gm = l >> 2, kq = l & 3;
    const int warpM = (w >> 1) * 32, warpN = (w & 1) * 64;
    const int rowBase = blockIdx.y * 128, colBase = blockIdx.x * 128;

    float acc[2][8][4];
#pragma unroll
    for (int i = 0; i < 2; ++i)
#pragma unroll
        for (int j = 0; j < 8; ++j)
#pragma unroll
            for (int e = 0; e < 4; ++e) acc[i][j][e] = 0.f;

    const int ar = t >> 1, ac = (t & 1) * 8;
    const int bk = t >> 4, bc = (t & 15) * 8;

    cp16(&As[0][ar][ac],     A + (size_t)(rowBase + ar) * ND + ac);
    cp16(&As[0][ar][ac + 4], A + (size_t)(rowBase + ar) * ND + ac + 4);
    cp16(&Bs[0][bk][bc],     W + (size_t)bk * ND + colBase + bc);
    cp16(&Bs[0][bk][bc + 4], W + (size_t)bk * ND + colBase + bc + 4);
    cp_commit();

    for (int c = 0; c < ND / 16; ++c) {
        if (c + 1 < ND / 16) {
            int k0 = (c + 1) * 16, s = (c + 1) & 1;
            cp16(&As[s][ar][ac],     A + (size_t)(rowBase + ar) * ND + k0 + ac);
            cp16(&As[s][ar][ac + 4], A + (size_t)(rowBase + ar) * ND + k0 + ac + 4);
            cp16(&Bs[s][bk][bc],     W + (size_t)(k0 + bk) * ND + colBase + bc);
            cp16(&Bs[s][bk][bc + 4], W + (size_t)(k0 + bk) * ND + colBase + bc + 4);
            cp_commit();
            cp_wait1();
        } else {
            cp_wait0();
        }
        __syncthreads();

        const int s = c & 1;
#pragma unroll
        for (int ks = 0; ks < 2; ++ks) {
            const int k = ks * 8;
            float a[2][4], b[8][2];
#pragma unroll
            for (int mt = 0; mt < 2; ++mt) {
                int m = warpM + mt * 16 + gm;
                a[mt][0] = f2tf(As[s][m][k + kq]);
                a[mt][1] = f2tf(As[s][m + 8][k + kq]);
                a[mt][2] = f2tf(As[s][m][k + kq + 4]);
                a[mt][3] = f2tf(As[s][m + 8][k + kq + 4]);
            }
#pragma unroll
            for (int nt = 0; nt < 8; ++nt) {
                int n = warpN + nt * 8 + gm;
                b[nt][0] = f2tf(Bs[s][k + kq][n]);
                b[nt][1] = f2tf(Bs[s][k + kq + 4][n]);
            }
#pragma unroll
            for (int mt = 0; mt < 2; ++mt)
#pragma unroll
                for (int nt = 0; nt < 8; ++nt)
                    mma_tf32(acc[mt][nt], a[mt], b[nt]);
        }
        __syncthreads();
    }

#pragma unroll
    for (int mt = 0; mt < 2; ++mt) {
#pragma unroll
        for (int nt = 0; nt < 8; ++nt) {
            int r0 = rowBase + warpM + mt * 16 + gm;
            int c0 = colBase + warpN + nt * 8 + kq * 2;
#pragma unroll
            for (int half = 0; half < 2; ++half) {
                int r = r0 + half * 8;
                float v0 = acc[mt][nt][half * 2 + 0] + bias[c0];
                float v1 = acc[mt][nt][half * 2 + 1] + bias[c0 + 1];
                if (splitR == 0) {
                    *(float2*)&C[(size_t)r * ND + c0] = make_float2(v0, v1);
                } else {
                    v0 = f2tf(v0); v1 = f2tf(v1);
                    int h = c0 >> 6, d = c0 & 63;
                    int bb = r / splitR, rr = r - bb * splitR;
                    *(float2*)&C[(((size_t)bb * NH + h) * splitR + rr) * HD + d] =
                        make_float2(v0, v1);
                }
            }
        }
    }
}

// ============================================================================
// nt64_pair_tf32: c2p and p2c in one launch (round-10 structure: 2-stage
// K-chunk-16 cp.async pipeline — measured 103us; r12 loader reverted).
// z<64:  C2P[z][i][kk] = q[z] . posk[z%16]      (bf16 out, pre-scaled sqrt(1.5))
// z>=64: P2C[z-64][i][kk] = k[z-64] . posq[..]  (bf16 out, pre-scaled sqrt(1.5))
// ============================================================================
__global__ __launch_bounds__(256, 2) void nt64_pair_tf32(
    const float* __restrict__ q, const float* __restrict__ posk,
    const float* __restrict__ kk, const float* __restrict__ posq,
    __nv_bfloat16* __restrict__ c2p, __nv_bfloat16* __restrict__ p2c)
{
    __shared__ float As[2][128][20];
    __shared__ float Bs[2][128][20];

    const int t = threadIdx.x, l = t & 31, w = t >> 5;
    const int gm = l >> 2, kq = l & 3;
    const int warpM = (w >> 1) * 32, warpN = (w & 1) * 64;
    const int zz = blockIdx.z;
    const int batch = zz & 63;
    const int iBase = blockIdx.y * 128, jBase = blockIdx.x * 128;

    const float* Ab = ((zz < 64) ? q : kk) + (size_t)batch * NS * HD;
    const float* Bb = ((zz < 64) ? posk : posq) + (size_t)(batch & 15) * NK2 * HD;
    __nv_bfloat16* Cb = ((zz < 64) ? c2p : p2c) + (size_t)batch * NS * NK2;

    float acc[2][8][4];
#pragma unroll
    for (int i = 0; i < 2; ++i)
#pragma unroll
        for (int j = 0; j < 8; ++j)
#pragma unroll
            for (int e = 0; e < 4; ++e) acc[i][j][e] = 0.f;

    const int sr = t >> 1, sc = (t & 1) * 8;

    cp16(&As[0][sr][sc],     Ab + (size_t)(iBase + sr) * HD + sc);
    cp16(&As[0][sr][sc + 4], Ab + (size_t)(iBase + sr) * HD + sc + 4);
    cp16(&Bs[0][sr][sc],     Bb + (size_t)(jBase + sr) * HD + sc);
    cp16(&Bs[0][sr][sc + 4], Bb + (size_t)(jBase + sr) * HD + sc + 4);
    cp_commit();

#pragma unroll
    for (int c = 0; c < 4; ++c) {
        if (c + 1 < 4) {
            int d0 = (c + 1) * 16, s = (c + 1) & 1;
            cp16(&As[s][sr][sc],     Ab + (size_t)(iBase + sr) * HD + d0 + sc);
            cp16(&As[s][sr][sc + 4], Ab + (size_t)(iBase + sr) * HD + d0 + sc + 4);
            cp16(&Bs[s][sr][sc],     Bb + (size_t)(jBase + sr) * HD + d0 + sc);
            cp16(&Bs[s][sr][sc + 4], Bb + (size_t)(jBase + sr) * HD + d0 + sc + 4);
            cp_commit();
            cp_wait1();
        } else {
            cp_wait0();
        }
        __syncthreads();

        const int s = c & 1;
#pragma unroll
        for (int ks = 0; ks < 2; ++ks) {
            const int k = ks * 8;
            float a[2][4], b[8][2];
#pragma unroll
            for (int mt = 0; mt < 2; ++mt) {
                int m = warpM + mt * 16 + gm;
                a[mt][0] = As[s][m][k + kq];
                a[mt][1] = As[s][m + 8][k + kq];
                a[mt][2] = As[s][m][k + kq + 4];
                a[mt][3] = As[s][m + 8][k + kq + 4];
            }
#pragma unroll
            for (int nt = 0; nt < 8; ++nt) {
                int n = warpN + nt * 8 + gm;
                b[nt][0] = Bs[s][n][k + kq];
                b[nt][1] = Bs[s][n][k + kq + 4];
            }
#pragma unroll
            for (int mt = 0; mt < 2; ++mt)
#pragma unroll
                for (int nt = 0; nt < 8; ++nt)
                    mma_tf32(acc[mt][nt], a[mt], b[nt]);
        }
        __syncthreads();
    }

    // store pre-scaled by inv128/inv192 = sqrt(1.5): flash folds inv192 into exp
    const float sstore = 1.2247448713915890f;
#pragma unroll
    for (int mt = 0; mt < 2; ++mt)
#pragma unroll
        for (int nt = 0; nt < 8; ++nt) {
            int r0 = iBase + warpM + mt * 16 + gm;
            int c0 = jBase + warpN + nt * 8 + kq * 2;
#pragma unroll
            for (int half = 0; half < 2; ++half) {
                __nv_bfloat162 pk;
                pk.x = __float2bfloat16(acc[mt][nt][half * 2 + 0] * sstore);
                pk.y = __float2bfloat16(acc[mt][nt][half * 2 + 1] * sstore);
                *(__nv_bfloat162*)&Cb[(size_t)(r0 + half * 8) * NK2 + c0] = pk;
            }
        }
}

// ============================================================================
// flash_tf32: fused scores(QK^T + rel-pos bias) -> online softmax -> PV.
// Bias gathers INITIALIZE the S accumulator before the K-tile wait (overlap).
// inv192 folded into exp args; softmax state in raw units. (round-12, kept)
// ============================================================================
__global__ __launch_bounds__(256, 1) void flash_tf32(
    const float* __restrict__ q, const float* __restrict__ k,
    const float* __restrict__ v,
    const __nv_bfloat16* __restrict__ c2p, const __nv_bfloat16* __restrict__ p2c,
    const int2* __restrict__ idxt, float* __restrict__ ctx)
{
    extern __shared__ float smf[];
    float (*X0)[72] = (float(*)[72])smf;
    float (*X1)[72] = (float(*)[72])(smf + 128 * 72);

    const int t = threadIdx.x, l = t & 31, w = t >> 5;
    const int gm = l >> 2, kq = l & 3;
    const int warpM = w * 16;
    const int z = blockIdx.y;
    const int bz = z >> 4, h = z & 15;
    const int iBase = blockIdx.x * 128;

    const float* Qb = q + (size_t)z * NS * HD;
    const float* Kb = k + (size_t)z * NS * HD;
    const float* Vb = v + (size_t)z * NS * HD;
    const __nv_bfloat16* c2pr = c2p + (size_t)z * NS * NK2;
    const __nv_bfloat16* p2cr = p2c + (size_t)z * NS * NK2;

    const int sr = t >> 1, cb = (t & 1) * 32;
    const int i0 = iBase + warpM + gm;
    const int i1 = i0 + 8;

    // ---- load Q tile -> X0, extract fragments ----
#pragma unroll
    for (int i = 0; i < 8; ++i)
        cp16(&X0[sr][cb + i * 4], Qb + (size_t)(iBase + sr) * HD + cb + i * 4);
    cp_commit(); cp_wait0();
    __syncthreads();

    float aq[8][4];
    {
        int m = warpM + gm;
#pragma unroll
        for (int ks = 0; ks < 8; ++ks) {
            int kk = ks * 8;
            aq[ks][0] = X0[m][kk + kq];
            aq[ks][1] = X0[m + 8][kk + kq];
            aq[ks][2] = X0[m][kk + kq + 4];
            aq[ks][3] = X0[m + 8][kk + kq + 4];
        }
    }
    __syncthreads();

    // prefetch K(0) -> X0
#pragma unroll
    for (int i = 0; i < 8; ++i)
        cp16(&X0[sr][cb + i * 4], Kb + (size_t)sr * HD + cb + i * 4);
    cp_commit();   // pending: [K0]

    float m0 = -INFINITY, m1 = -INFINITY, l0 = 0.f, l1 = 0.f;   // raw units
    float o[8][4];
#pragma unroll
    for (int i = 0; i < 8; ++i)
#pragma unroll
        for (int e = 0; e < 4; ++e) o[i][e] = 0.f;

    const float inv192 = 0.07216878364870322f;  // 1/sqrt(64*3)
    const int srcA = (l & ~3) | (kq >> 1);
    const int srcB = srcA + 2;
    const bool odd = (kq & 1);

    for (int jt = 0; jt < 8; ++jt) {
        const int jBase = jt * 128;

        // issue V(jt) -> X1
#pragma unroll
        for (int i = 0; i < 8; ++i)
            cp16(&X1[sr][cb + i * 4], Vb + (size_t)(jBase + sr) * HD + cb + i * 4);
        cp_commit();        // pending: [K(jt), V(jt)]

        // ---- bias gathers initialize S (overlap with K(jt) in flight) ----
        float sc[16][4];
#pragma unroll
        for (int nt = 0; nt < 16; ++nt) {
#pragma unroll
            for (int e = 0; e < 4; ++e) {
                int i = (e < 2) ? i0 : i1;
                int j = jBase + nt * 8 + kq * 2 + (e & 1);
                int2 ip = idxt[i - j + (NS - 1)];
                sc[nt][e] = __bfloat162float(c2pr[(size_t)i * NK2 + ip.x])
                          + __bfloat162float(p2cr[(size_t)j * NK2 + ip.y]);
            }
        }

        cp_wait1();         // K(jt) resident
        __syncthreads();

        // ---- S += Q K^T ----
#pragma unroll
        for (int ks = 0; ks < 8; ++ks) {
            const int kk = ks * 8;
#pragma unroll
            for (int nt = 0; nt < 16; ++nt) {
                int n = nt * 8 + gm;
                float b[2];
                b[0] = X0[n][kk + kq];
                b[1] = X0[n][kk + kq + 4];
                mma_tf32(sc[nt], aq[ks], b);
            }
        }
        __syncthreads();

        // prefetch K(jt+1) -> X0 (overlaps softmax)
        if (jt + 1 < 8) {
#pragma unroll
            for (int i = 0; i < 8; ++i)
                cp16(&X0[sr][cb + i * 4],
                     Kb + (size_t)((jt + 1) * 128 + sr) * HD + cb + i * 4);
            cp_commit();
        }

        // ---- online softmax (raw units; inv192 folded into exp args) ----
        float tm0 = -INFINITY, tm1 = -INFINITY;
#pragma unroll
        for (int nt = 0; nt < 16; ++nt) {
            tm0 = fmaxf(tm0, fmaxf(sc[nt][0], sc[nt][1]));
            tm1 = fmaxf(tm1, fmaxf(sc[nt][2], sc[nt][3]));
        }
        tm0 = fmaxf(tm0, __shfl_xor_sync(0xffffffffu, tm0, 1));
        tm0 = fmaxf(tm0, __shfl_xor_sync(0xffffffffu, tm0, 2));
        tm1 = fmaxf(tm1, __shfl_xor_sync(0xffffffffu, tm1, 1));
        tm1 = fmaxf(tm1, __shfl_xor_sync(0xffffffffu, tm1, 2));

        float mn0 = fmaxf(m0, tm0), mn1 = fmaxf(m1, tm1);
        float fac0 = expf((m0 - mn0) * inv192);
        float fac1 = expf((m1 - mn1) * inv192);
        m0 = mn0; m1 = mn1;

        float s0 = 0.f, s1 = 0.f;
#pragma unroll
        for (int nt = 0; nt < 16; ++nt) {
            sc[nt][0] = f2tf(expf((sc[nt][0] - mn0) * inv192));
            sc[nt][1] = f2tf(expf((sc[nt][1] - mn0) * inv192));
            sc[nt][2] = f2tf(expf((sc[nt][2] - mn1) * inv192));
            sc[nt][3] = f2tf(expf((sc[nt][3] - mn1) * inv192));
            s0 += sc[nt][0] + sc[nt][1];
            s1 += sc[nt][2] + sc[nt][3];
        }
        s0 += __shfl_xor_sync(0xffffffffu, s0, 1);
        s0 += __shfl_xor_sync(0xffffffffu, s0, 2);
        s1 += __shfl_xor_sync(0xffffffffu, s1, 1);
        s1 += __shfl_xor_sync(0xffffffffu, s1, 2);
        l0 = l0 * fac0 + s0;
        l1 = l1 * fac1 + s1;

#pragma unroll
        for (int nt = 0; nt < 8; ++nt) {
            o[nt][0] *= fac0; o[nt][1] *= fac0;
            o[nt][2] *= fac1; o[nt][3] *= fac1;
        }

        // ---- wait V(jt), then PV ----
        if (jt + 1 < 8) cp_wait1(); else cp_wait0();
        __syncthreads();

#pragma unroll
        for (int ksg = 0; ksg < 16; ++ksg) {
            float e0 = __shfl_sync(0xffffffffu, sc[ksg][0], srcA);
            float e1 = __shfl_sync(0xffffffffu, sc[ksg][1], srcA);
            float e2 = __shfl_sync(0xffffffffu, sc[ksg][2], srcA);
            float e3 = __shfl_sync(0xffffffffu, sc[ksg][3], srcA);
            float f0 = __shfl_sync(0xffffffffu, sc[ksg][0], srcB);
            float f1 = __shfl_sync(0xffffffffu, sc[ksg][1], srcB);
            float f2 = __shfl_sync(0xffffffffu, sc[ksg][2], srcB);
            float f3 = __shfl_sync(0xffffffffu, sc[ksg][3], srcB);
            float pa[4];
            pa[0] = odd ? e1 : e0;
            pa[1] = odd ? e3 : e2;
            pa[2] = odd ? f1 : f0;
            pa[3] = odd ? f3 : f2;
#pragma unroll
            for (int nt = 0; nt < 8; ++nt) {
                int n = nt * 8 + gm;
                float b[2];
                b[0] = X1[ksg * 8 + kq][n];
                b[1] = X1[ksg * 8 + kq + 4][n];
                mma_tf32(o[nt], pa, b);
            }
        }
        __syncthreads();
    }

    // ---- normalize and store ctx ----
    float r0 = 1.0f / l0, r1 = 1.0f / l1;
#pragma unroll
    for (int nt = 0; nt < 8; ++nt) {
        int c0 = nt * 8 + kq * 2;
        *(float2*)&ctx[((size_t)bz * NS + i0) * ND + h * HD + c0] =
            make_float2(o[nt][0] * r0, o[nt][1] * r0);
        *(float2*)&ctx[((size_t)bz * NS + i1) * ND + h * HD + c0] =
            make_float2(o[nt][2] * r1, o[nt][3] * r1);
    }
}

// ---------------- launch ----------------
extern "C" void kernel_launch(void* const* d_in, const int* in_sizes, int n_in,
                              void* d_out, int out_size) {
    const float* hs    = (const float*)d_in[0];
    const float* Wq    = (const float*)d_in[1];
    const float* bq    = (const float*)d_in[2];
    const float* Wk    = (const float*)d_in[3];
    const float* bk    = (const float*)d_in[4];
    const float* Wv    = (const float*)d_in[5];
    const float* bv    = (const float*)d_in[6];
    const float* Wo    = (const float*)d_in[7];
    const float* bo    = (const float*)d_in[8];
    const float* rel   = (const float*)d_in[9];
    const float* ln_g  = (const float*)d_in[10];
    const float* ln_b  = (const float*)d_in[11];
    const float* Wpk   = (const float*)d_in[12];
    const float* bpk   = (const float*)d_in[13];
    const float* Wpq   = (const float*)d_in[14];
    const float* bpq   = (const float*)d_in[15];
    float* out = (float*)d_out;

    float *p_re, *p_q, *p_k, *p_v, *p_posk, *p_posq, *p_ctx;
    __nv_bfloat16 *p_c2p, *p_p2c;
    int2* p_idx;
    cudaGetSymbolAddress((void**)&p_re, g_re);
    cudaGetSymbolAddress((void**)&p_q, g_q);
    cudaGetSymbolAddress((void**)&p_k, g_k);
    cudaGetSymbolAddress((void**)&p_v, g_v);
    cudaGetSymbolAddress((void**)&p_posk, g_posk);
    cudaGetSymbolAddress((void**)&p_posq, g_posq);
    cudaGetSymbolAddress((void**)&p_c2p, g_c2p);
    cudaGetSymbolAddress((void**)&p_p2c, g_p2c);
    cudaGetSymbolAddress((void**)&p_ctx, g_ctx);
    cudaGetSymbolAddress((void**)&p_idx, g_idx);

    static bool attr_done = false;
    if (!attr_done) {
        cudaFuncSetAttribute(flash_tf32,
                             cudaFuncAttributeMaxDynamicSharedMemorySize, 73728);
        attr_done = true;
    }

    build_idx_kernel<<<9, 256>>>(p_idx);
    ln_kernel<<<NK2, 256>>>(rel, ln_g, ln_b, p_re);

    // merged Q/K/V + pos-k/pos-q projections in one launch
    MMJobs jobs;
    jobs.j[0] = { hs,   Wq,  bq,  p_q,    NB * NS, NS  };
    jobs.j[1] = { hs,   Wk,  bk,  p_k,    NB * NS, NS  };
    jobs.j[2] = { hs,   Wv,  bv,  p_v,    NB * NS, NS  };
    jobs.j[3] = { p_re, Wpk, bpk, p_posk, NK2,     NK2 };
    jobs.j[4] = { p_re, Wpq, bpq, p_posq, NK2,     NK2 };
    mm_jobs_tf32<<<dim3(8, 32, 5), 256>>>(jobs);

    // c2p and p2c in one launch (bf16, pre-scaled by sqrt(1.5))
    nt64_pair_tf32<<<dim3(4, 8, 128), 256>>>(p_q, p_posk, p_k, p_posq, p_c2p, p_p2c);

    // fused attention
    flash_tf32<<<dim3(8, 64), 256, 73728>>>(p_q, p_k, p_v, p_c2p, p_p2c, p_idx, p_ctx);

    // out = ctx @ Wo + bo
    MMJobs jo;
    jo.j[0] = { p_ctx, Wo, bo, out, NB * NS, 0 };
    jo.j[1] = jo.j[0]; jo.j[2] = jo.j[0]; jo.j[3] = jo.j[0]; jo.j[4] = jo.j[0];
    mm_jobs_tf32<<<dim3(8, 32, 1), 256>>>(jo);
}

// round 14
// speedup vs baseline: 1.0526x; 1.0147x over previous
#include <cuda_runtime.h>
#include <cuda_bf16.h>
#include <math.h>

// Shapes (fixed by the problem)
#define NB 4
#define NH 16
#define NS 1024
#define ND 1024
#define HD 64
#define NK2 512   // 2 * BUCKETS
#define SPAN 256  // BUCKETS

// ---------------- scratch (device globals; no allocs allowed) ----------------
__device__ float g_re[NK2 * ND];
__device__ float g_q[(size_t)NB * NH * NS * HD];
__device__ float g_k[(size_t)NB * NH * NS * HD];
__device__ float g_v[(size_t)NB * NH * NS * HD];
__device__ float g_posk[NH * NK2 * HD];
__device__ float g_posq[NH * NK2 * HD];
__device__ __nv_bfloat16 g_c2p[(size_t)NB * NH * NS * NK2];  // pre-scaled sqrt(1.5)
__device__ __nv_bfloat16 g_p2c[(size_t)NB * NH * NS * NK2];  // pre-scaled sqrt(1.5)
__device__ float g_ctx[(size_t)NB * NS * ND];
__device__ int2  g_idx[2 * NS - 1];   // (idx1, idx2) per delta

// ---------------- helpers ----------------
__device__ __forceinline__ float f2tf(float x) {
    unsigned u;
    asm("cvt.rna.tf32.f32 %0, %1;" : "=r"(u) : "f"(x));
    return __uint_as_float(u);
}

__device__ __forceinline__ void mma_tf32(float* c, const float* a, const float* b) {
    asm volatile("mma.sync.aligned.m16n8k8.row.col.f32.tf32.tf32.f32 "
                 "{%0,%1,%2,%3}, {%4,%5,%6,%7}, {%8,%9}, {%0,%1,%2,%3};\n"
                 : "+f"(c[0]), "+f"(c[1]), "+f"(c[2]), "+f"(c[3])
                 : "r"(__float_as_uint(a[0])), "r"(__float_as_uint(a[1])),
                   "r"(__float_as_uint(a[2])), "r"(__float_as_uint(a[3])),
                   "r"(__float_as_uint(b[0])), "r"(__float_as_uint(b[1])));
}

__device__ __forceinline__ void cp16(float* dst, const float* src) {
    unsigned s = (unsigned)__cvta_generic_to_shared(dst);
    asm volatile("cp.async.cg.shared.global [%0], [%1], 16;" :: "r"(s), "l"(src));
}
__device__ __forceinline__ void cp_commit() { asm volatile("cp.async.commit_group;"); }
__device__ __forceinline__ void cp_wait0()  { asm volatile("cp.async.wait_group 0;"); }
__device__ __forceinline__ void cp_wait1()  { asm volatile("cp.async.wait_group 1;"); }
__device__ __forceinline__ void cp_wait2()  { asm volatile("cp.async.wait_group 2;"); }

// ---------------- bucket + index table (matches jax f32 semantics) -----------
__device__ __forceinline__ int bucketf(int rel) {
    const float mid = 128.0f;
    float signf = (rel > 0) ? 1.0f : (rel < 0 ? -1.0f : 0.0f);
    float abs_pos = (rel < 128 && rel > -128) ? 127.0f : fabsf((float)rel);
    float bucket;
    if (abs_pos <= mid) {
        bucket = (float)rel;
    } else {
        const float LOGC = 1.3843393289f;  // log(511/128) as f32
        float log_pos = ceilf(logf(abs_pos / mid) / LOGC * 127.0f) + mid;
        bucket = log_pos * signf;
    }
    return (int)bucket;
}

__global__ void build_idx_kernel(int2* idx) {
    int i = blockIdx.x * blockDim.x + threadIdx.x;
    if (i >= 2 * NS - 1) return;
    int rel = i - (NS - 1);          // delta = i - j
    int b1 = bucketf(rel);
    int b2 = bucketf(-rel);
    int2 v;
    v.x = min(max(b1 + SPAN, 0), 2 * SPAN - 1);
    v.y = min(max(SPAN - b2, 0), 2 * SPAN - 1);
    idx[i] = v;
}

// ---------------- LayerNorm for rel_emb [512,1024] ----------------
__global__ void ln_kernel(const float* __restrict__ x, const float* __restrict__ g,
                          const float* __restrict__ b, float* __restrict__ y) {
    int row = blockIdx.x;
    const float* xr = x + (size_t)row * ND;
    __shared__ float red[256];
    int tid = threadIdx.x;

    float s = 0.f;
    for (int i = tid; i < ND; i += 256) s += xr[i];
    red[tid] = s; __syncthreads();
    for (int o = 128; o > 0; o >>= 1) { if (tid < o) red[tid] += red[tid + o]; __syncthreads(); }
    float mu = red[0] * (1.0f / ND);
    __syncthreads();

    float v = 0.f;
    for (int i = tid; i < ND; i += 256) { float d = xr[i] - mu; v += d * d; }
    red[tid] = v; __syncthreads();
    for (int o = 128; o > 0; o >>= 1) { if (tid < o) red[tid] += red[tid + o]; __syncthreads(); }
    float var = red[0] * (1.0f / ND);
    float inv = 1.0f / sqrtf(var + 1e-5f);

    for (int i = tid; i < ND; i += 256)
        y[(size_t)row * ND + i] = (xr[i] - mu) * inv * g[i] + b[i];
}

// ============================================================================
// mm_jobs_tf32: up to 5 independent GEMMs C = A[M,1024] @ W[1024,1024] + bias.
// 128x128 tile, K-chunk 16, THREE-stage cp.async ring (prefetch distance 2),
// double-barrier per chunk (hazard-safe), dynamic smem 56832 B, 2 CTAs/SM.
// ============================================================================
struct MMJob {
    const float* A; const float* W; const float* bias; float* C;
    int M; int splitR;
};
struct MMJobs { MMJob j[5]; };

#define MMA_ST 2560   // 128*20 floats per A stage
#define MMB_ST 2176   // 16*136 floats per B stage
#define MM_SMEM ((3 * (MMA_ST + MMB_ST)) * 4)   // 56832 bytes

__global__ __launch_bounds__(256, 2) void mm_jobs_tf32(MMJobs jobs)
{
    extern __shared__ float sm[];
    float* Asm = sm;                  // 3 stages of [128][20]
    float* Bsm = sm + 3 * MMA_ST;     // 3 stages of [16][136]

    const MMJob jb = jobs.j[blockIdx.z];
    if (blockIdx.y * 128 >= jb.M) return;
    const float* A = jb.A; const float* W = jb.W;
    const float* bias = jb.bias; float* C = jb.C;
    const int splitR = jb.splitR;

    const int t = threadIdx.x, l = t & 31, w = t >> 5;
    const int gm = l >> 2, kq = l & 3;
    const int warpM = (w >> 1) * 32, warpN = (w & 1) * 64;
    const int rowBase = blockIdx.y * 128, colBase = blockIdx.x * 128;

    float acc[2][8][4];
#pragma unroll
    for (int i = 0; i < 2; ++i)
#pragma unroll
        for (int j = 0; j < 8; ++j)
#pragma unroll
            for (int e = 0; e < 4; ++e) acc[i][j][e] = 0.f;

    const int ar = t >> 1, ac = (t & 1) * 8;
    const int bk = t >> 4, bc = (t & 15) * 8;

    // prologue: chunks 0,1 -> stages 0,1
#pragma unroll
    for (int p = 0; p < 2; ++p) {
        int k0 = p * 16;
        cp16(&Asm[p * MMA_ST + ar * 20 + ac],     A + (size_t)(rowBase + ar) * ND + k0 + ac);
        cp16(&Asm[p * MMA_ST + ar * 20 + ac + 4], A + (size_t)(rowBase + ar) * ND + k0 + ac + 4);
        cp16(&Bsm[p * MMB_ST + bk * 136 + bc],     W + (size_t)(k0 + bk) * ND + colBase + bc);
        cp16(&Bsm[p * MMB_ST + bk * 136 + bc + 4], W + (size_t)(k0 + bk) * ND + colBase + bc + 4);
        cp_commit();
    }

    int stC = 0;          // compute stage = c % 3
    int stI = 2;          // issue stage  = (c+2) % 3
    for (int c = 0; c < 64; ++c) {
        if (c + 2 < 64) {
            int k0 = (c + 2) * 16;
            cp16(&Asm[stI * MMA_ST + ar * 20 + ac],     A + (size_t)(rowBase + ar) * ND + k0 + ac);
            cp16(&Asm[stI * MMA_ST + ar * 20 + ac + 4], A + (size_t)(rowBase + ar) * ND + k0 + ac + 4);
            cp16(&Bsm[stI * MMB_ST + bk * 136 + bc],     W + (size_t)(k0 + bk) * ND + colBase + bc);
            cp16(&Bsm[stI * MMB_ST + bk * 136 + bc + 4], W + (size_t)(k0 + bk) * ND + colBase + bc + 4);
            cp_commit();
            cp_wait2();
        } else if (c + 1 < 64) {
            cp_wait1();
        } else {
            cp_wait0();
        }
        __syncthreads();

        const float* Ast = &Asm[stC * MMA_ST];
        const float* Bst = &Bsm[stC * MMB_ST];
#pragma unroll
        for (int ks = 0; ks < 2; ++ks) {
            const int k = ks * 8;
            float a[2][4], b[8][2];
#pragma unroll
            for (int mt = 0; mt < 2; ++mt) {
                int m = warpM + mt * 16 + gm;
                a[mt][0] = f2tf(Ast[m * 20 + k + kq]);
                a[mt][1] = f2tf(Ast[(m + 8) * 20 + k + kq]);
                a[mt][2] = f2tf(Ast[m * 20 + k + kq + 4]);
                a[mt][3] = f2tf(Ast[(m + 8) * 20 + k + kq + 4]);
            }
#pragma unroll
            for (int nt = 0; nt < 8; ++nt) {
                int n = warpN + nt * 8 + gm;
                b[nt][0] = f2tf(Bst[(k + kq) * 136 + n]);
                b[nt][1] = f2tf(Bst[(k + kq + 4) * 136 + n]);
            }
#pragma unroll
            for (int mt = 0; mt < 2; ++mt)
#pragma unroll
                for (int nt = 0; nt < 8; ++nt)
                    mma_tf32(acc[mt][nt], a[mt], b[nt]);
        }
        __syncthreads();

        stC = (stC == 2) ? 0 : stC + 1;
        stI = (stI == 2) ? 0 : stI + 1;
    }

#pragma unroll
    for (int mt = 0; mt < 2; ++mt) {
#pragma unroll
        for (int nt = 0; nt < 8; ++nt) {
            int r0 = rowBase + warpM + mt * 16 + gm;
            int c0 = colBase + warpN + nt * 8 + kq * 2;
#pragma unroll
            for (int half = 0; half < 2; ++half) {
                int r = r0 + half * 8;
                float v0 = acc[mt][nt][half * 2 + 0] + bias[c0];
                float v1 = acc[mt][nt][half * 2 + 1] + bias[c0 + 1];
                if (splitR == 0) {
                    *(float2*)&C[(size_t)r * ND + c0] = make_float2(v0, v1);
                } else {
                    v0 = f2tf(v0); v1 = f2tf(v1);
                    int h = c0 >> 6, d = c0 & 63;
                    int bb = r / splitR, rr = r - bb * splitR;
                    *(float2*)&C[(((size_t)bb * NH + h) * splitR + rr) * HD + d] =
                        make_float2(v0, v1);
                }
            }
        }
    }
}

// ============================================================================
// nt64_pair_tf32: c2p and p2c in one launch (round-10/13 structure, 103us).
// ============================================================================
__global__ __launch_bounds__(256, 2) void nt64_pair_tf32(
    const float* __restrict__ q, const float* __restrict__ posk,
    const float* __restrict__ kk, const float* __restrict__ posq,
    __nv_bfloat16* __restrict__ c2p, __nv_bfloat16* __restrict__ p2c)
{
    __shared__ float As[2][128][20];
    __shared__ float Bs[2][128][20];

    const int t = threadIdx.x, l = t & 31, w = t >> 5;
    const int gm = l >> 2, kq = l & 3;
    const int warpM = (w >> 1) * 32, warpN = (w & 1) * 64;
    const int zz = blockIdx.z;
    const int batch = zz & 63;
    const int iBase = blockIdx.y * 128, jBase = blockIdx.x * 128;

    const float* Ab = ((zz < 64) ? q : kk) + (size_t)batch * NS * HD;
    const float* Bb = ((zz < 64) ? posk : posq) + (size_t)(batch & 15) * NK2 * HD;
    __nv_bfloat16* Cb = ((zz < 64) ? c2p : p2c) + (size_t)batch * NS * NK2;

    float acc[2][8][4];
#pragma unroll
    for (int i = 0; i < 2; ++i)
#pragma unroll
        for (int j = 0; j < 8; ++j)
#pragma unroll
            for (int e = 0; e < 4; ++e) acc[i][j][e] = 0.f;

    const int sr = t >> 1, sc = (t & 1) * 8;

    cp16(&As[0][sr][sc],     Ab + (size_t)(iBase + sr) * HD + sc);
    cp16(&As[0][sr][sc + 4], Ab + (size_t)(iBase + sr) * HD + sc + 4);
    cp16(&Bs[0][sr][sc],     Bb + (size_t)(jBase + sr) * HD + sc);
    cp16(&Bs[0][sr][sc + 4], Bb + (size_t)(jBase + sr) * HD + sc + 4);
    cp_commit();

#pragma unroll
    for (int c = 0; c < 4; ++c) {
        if (c + 1 < 4) {
            int d0 = (c + 1) * 16, s = (c + 1) & 1;
            cp16(&As[s][sr][sc],     Ab + (size_t)(iBase + sr) * HD + d0 + sc);
            cp16(&As[s][sr][sc + 4], Ab + (size_t)(iBase + sr) * HD + d0 + sc + 4);
            cp16(&Bs[s][sr][sc],     Bb + (size_t)(jBase + sr) * HD + d0 + sc);
            cp16(&Bs[s][sr][sc + 4], Bb + (size_t)(jBase + sr) * HD + d0 + sc + 4);
            cp_commit();
            cp_wait1();
        } else {
            cp_wait0();
        }
        __syncthreads();

        const int s = c & 1;
#pragma unroll
        for (int ks = 0; ks < 2; ++ks) {
            const int k = ks * 8;
            float a[2][4], b[8][2];
#pragma unroll
            for (int mt = 0; mt < 2; ++mt) {
                int m = warpM + mt * 16 + gm;
                a[mt][0] = As[s][m][k + kq];
                a[mt][1] = As[s][m + 8][k + kq];
                a[mt][2] = As[s][m][k + kq + 4];
                a[mt][3] = As[s][m + 8][k + kq + 4];
            }
#pragma unroll
            for (int nt = 0; nt < 8; ++nt) {
                int n = warpN + nt * 8 + gm;
                b[nt][0] = Bs[s][n][k + kq];
                b[nt][1] = Bs[s][n][k + kq + 4];
            }
#pragma unroll
            for (int mt = 0; mt < 2; ++mt)
#pragma unroll
                for (int nt = 0; nt < 8; ++nt)
                    mma_tf32(acc[mt][nt], a[mt], b[nt]);
        }
        __syncthreads();
    }

    const float sstore = 1.2247448713915890f;  // sqrt(1.5)
#pragma unroll
    for (int mt = 0; mt < 2; ++mt)
#pragma unroll
        for (int nt = 0; nt < 8; ++nt) {
            int r0 = iBase + warpM + mt * 16 + gm;
            int c0 = jBase + warpN + nt * 8 + kq * 2;
#pragma unroll
            for (int half = 0; half < 2; ++half) {
                __nv_bfloat162 pk;
                pk.x = __float2bfloat16(acc[mt][nt][half * 2 + 0] * sstore);
                pk.y = __float2bfloat16(acc[mt][nt][half * 2 + 1] * sstore);
                *(__nv_bfloat162*)&Cb[(size_t)(r0 + half * 8) * NK2 + c0] = pk;
            }
        }
}

// ============================================================================
// flash_tf32: fused scores(QK^T + rel-pos bias) -> online softmax -> PV.
// Bias gathers init S before the K-tile wait; __expf for all exponentials.
// ============================================================================
__global__ __launch_bounds__(256, 1) void flash_tf32(
    const float* __restrict__ q, const float* __restrict__ k,
    const float* __restrict__ v,
    const __nv_bfloat16* __restrict__ c2p, const __nv_bfloat16* __restrict__ p2c,
    const int2* __restrict__ idxt, float* __restrict__ ctx)
{
    extern __shared__ float smf[];
    float (*X0)[72] = (float(*)[72])smf;
    float (*X1)[72] = (float(*)[72])(smf + 128 * 72);

    const int t = threadIdx.x, l = t & 31, w = t >> 5;
    const int gm = l >> 2, kq = l & 3;
    const int warpM = w * 16;
    const int z = blockIdx.y;
    const int bz = z >> 4, h = z & 15;
    const int iBase = blockIdx.x * 128;

    const float* Qb = q + (size_t)z * NS * HD;
    const float* Kb = k + (size_t)z * NS * HD;
    const float* Vb = v + (size_t)z * NS * HD;
    const __nv_bfloat16* c2pr = c2p + (size_t)z * NS * NK2;
    const __nv_bfloat16* p2cr = p2c + (size_t)z * NS * NK2;

    const int sr = t >> 1, cb = (t & 1) * 32;
    const int i0 = iBase + warpM + gm;
    const int i1 = i0 + 8;

    // ---- load Q tile -> X0, extract fragments ----
#pragma unroll
    for (int i = 0; i < 8; ++i)
        cp16(&X0[sr][cb + i * 4], Qb + (size_t)(iBase + sr) * HD + cb + i * 4);
    cp_commit(); cp_wait0();
    __syncthreads();

    float aq[8][4];
    {
        int m = warpM + gm;
#pragma unroll
        for (int ks = 0; ks < 8; ++ks) {
            int kk = ks * 8;
            aq[ks][0] = X0[m][kk + kq];
            aq[ks][1] = X0[m + 8][kk + kq];
            aq[ks][2] = X0[m][kk + kq + 4];
            aq[ks][3] = X0[m + 8][kk + kq + 4];
        }
    }
    __syncthreads();

    // prefetch K(0) -> X0
#pragma unroll
    for (int i = 0; i < 8; ++i)
        cp16(&X0[sr][cb + i * 4], Kb + (size_t)sr * HD + cb + i * 4);
    cp_commit();   // pending: [K0]

    float m0 = -INFINITY, m1 = -INFINITY, l0 = 0.f, l1 = 0.f;   // raw units
    float o[8][4];
#pragma unroll
    for (int i = 0; i < 8; ++i)
#pragma unroll
        for (int e = 0; e < 4; ++e) o[i][e] = 0.f;

    const float inv192 = 0.07216878364870322f;  // 1/sqrt(64*3)
    const int srcA = (l & ~3) | (kq >> 1);
    const int srcB = srcA + 2;
    const bool odd = (kq & 1);

    for (int jt = 0; jt < 8; ++jt) {
        const int jBase = jt * 128;

        // issue V(jt) -> X1
#pragma unroll
        for (int i = 0; i < 8; ++i)
            cp16(&X1[sr][cb + i * 4], Vb + (size_t)(jBase + sr) * HD + cb + i * 4);
        cp_commit();        // pending: [K(jt), V(jt)]

        // ---- bias gathers initialize S (overlap with K(jt) in flight) ----
        float sc[16][4];
#pragma unroll
        for (int nt = 0; nt < 16; ++nt) {
#pragma unroll
            for (int e = 0; e < 4; ++e) {
                int i = (e < 2) ? i0 : i1;
                int j = jBase + nt * 8 + kq * 2 + (e & 1);
                int2 ip = idxt[i - j + (NS - 1)];
                sc[nt][e] = __bfloat162float(c2pr[(size_t)i * NK2 + ip.x])
                          + __bfloat162float(p2cr[(size_t)j * NK2 + ip.y]);
            }
        }

        cp_wait1();         // K(jt) resident
        __syncthreads();

        // ---- S += Q K^T ----
#pragma unroll
        for (int ks = 0; ks < 8; ++ks) {
            const int kk = ks * 8;
#pragma unroll
            for (int nt = 0; nt < 16; ++nt) {
                int n = nt * 8 + gm;
                float b[2];
                b[0] = X0[n][kk + kq];
                b[1] = X0[n][kk + kq + 4];
                mma_tf32(sc[nt], aq[ks], b);
            }
        }
        __syncthreads();

        // prefetch K(jt+1) -> X0 (overlaps softmax)
        if (jt + 1 < 8) {
#pragma unroll
            for (int i = 0; i < 8; ++i)
                cp16(&X0[sr][cb + i * 4],
                     Kb + (size_t)((jt + 1) * 128 + sr) * HD + cb + i * 4);
            cp_commit();
        }

        // ---- online softmax (raw units; inv192 folded into exp args) ----
        float tm0 = -INFINITY, tm1 = -INFINITY;
#pragma unroll
        for (int nt = 0; nt < 16; ++nt) {
            tm0 = fmaxf(tm0, fmaxf(sc[nt][0], sc[nt][1]));
            tm1 = fmaxf(tm1, fmaxf(sc[nt][2], sc[nt][3]));
        }
        tm0 = fmaxf(tm0, __shfl_xor_sync(0xffffffffu, tm0, 1));
        tm0 = fmaxf(tm0, __shfl_xor_sync(0xffffffffu, tm0, 2));
        tm1 = fmaxf(tm1, __shfl_xor_sync(0xffffffffu, tm1, 1));
        tm1 = fmaxf(tm1, __shfl_xor_sync(0xffffffffu, tm1, 2));

        float mn0 = fmaxf(m0, tm0), mn1 = fmaxf(m1, tm1);
        float fac0 = __expf((m0 - mn0) * inv192);
        float fac1 = __expf((m1 - mn1) * inv192);
        m0 = mn0; m1 = mn1;

        float s0 = 0.f, s1 = 0.f;
#pragma unroll
        for (int nt = 0; nt < 16; ++nt) {
            sc[nt][0] = f2tf(__expf((sc[nt][0] - mn0) * inv192));
            sc[nt][1] = f2tf(__expf((sc[nt][1] - mn0) * inv192));
            sc[nt][2] = f2tf(__expf((sc[nt][2] - mn1) * inv192));
            sc[nt][3] = f2tf(__expf((sc[nt][3] - mn1) * inv192));
            s0 += sc[nt][0] + sc[nt][1];
            s1 += sc[nt][2] + sc[nt][3];
        }
        s0 += __shfl_xor_sync(0xffffffffu, s0, 1);
        s0 += __shfl_xor_sync(0xffffffffu, s0, 2);
        s1 += __shfl_xor_sync(0xffffffffu, s1, 1);
        s1 += __shfl_xor_sync(0xffffffffu, s1, 2);
        l0 = l0 * fac0 + s0;
        l1 = l1 * fac1 + s1;

#pragma unroll
        for (int nt = 0; nt < 8; ++nt) {
            o[nt][0] *= fac0; o[nt][1] *= fac0;
            o[nt][2] *= fac1; o[nt][3] *= fac1;
        }

        // ---- wait V(jt), then PV ----
        if (jt + 1 < 8) cp_wait1(); else cp_wait0();
        __syncthreads();

#pragma unroll
        for (int ksg = 0; ksg < 16; ++ksg) {
            float e0 = __shfl_sync(0xffffffffu, sc[ksg][0], srcA);
            float e1 = __shfl_sync(0xffffffffu, sc[ksg][1], srcA);
            float e2 = __shfl_sync(0xffffffffu, sc[ksg][2], srcA);
            float e3 = __shfl_sync(0xffffffffu, sc[ksg][3], srcA);
            float f0 = __shfl_sync(0xffffffffu, sc[ksg][0], srcB);
            float f1 = __shfl_sync(0xffffffffu, sc[ksg][1], srcB);
            float f2 = __shfl_sync(0xffffffffu, sc[ksg][2], srcB);
            float f3 = __shfl_sync(0xffffffffu, sc[ksg][3], srcB);
            float pa[4];
            pa[0] = odd ? e1 : e0;
            pa[1] = odd ? e3 : e2;
            pa[2] = odd ? f1 : f0;
            pa[3] = odd ? f3 : f2;
#pragma unroll
            for (int nt = 0; nt < 8; ++nt) {
                int n = nt * 8 + gm;
                float b[2];
                b[0] = X1[ksg * 8 + kq][n];
                b[1] = X1[ksg * 8 + kq + 4][n];
                mma_tf32(o[nt], pa, b);
            }
        }
        __syncthreads();
    }

    // ---- normalize and store ctx ----
    float r0 = 1.0f / l0, r1 = 1.0f / l1;
#pragma unroll
    for (int nt = 0; nt < 8; ++nt) {
        int c0 = nt * 8 + kq * 2;
        *(float2*)&ctx[((size_t)bz * NS + i0) * ND + h * HD + c0] =
            make_float2(o[nt][0] * r0, o[nt][1] * r0);
        *(float2*)&ctx[((size_t)bz * NS + i1) * ND + h * HD + c0] =
            make_float2(o[nt][2] * r1, o[nt][3] * r1);
    }
}

// ---------------- launch ----------------
extern "C" void kernel_launch(void* const* d_in, const int* in_sizes, int n_in,
                              void* d_out, int out_size) {
    const float* hs    = (const float*)d_in[0];
    const float* Wq    = (const float*)d_in[1];
    const float* bq    = (const float*)d_in[2];
    const float* Wk    = (const float*)d_in[3];
    const float* bk    = (const float*)d_in[4];
    const float* Wv    = (const float*)d_in[5];
    const float* bv    = (const float*)d_in[6];
    const float* Wo    = (const float*)d_in[7];
    const float* bo    = (const float*)d_in[8];
    const float* rel   = (const float*)d_in[9];
    const float* ln_g  = (const float*)d_in[10];
    const float* ln_b  = (const float*)d_in[11];
    const float* Wpk   = (const float*)d_in[12];
    const float* bpk   = (const float*)d_in[13];
    const float* Wpq   = (const float*)d_in[14];
    const float* bpq   = (const float*)d_in[15];
    float* out = (float*)d_out;

    float *p_re, *p_q, *p_k, *p_v, *p_posk, *p_posq, *p_ctx;
    __nv_bfloat16 *p_c2p, *p_p2c;
    int2* p_idx;
    cudaGetSymbolAddress((void**)&p_re, g_re);
    cudaGetSymbolAddress((void**)&p_q, g_q);
    cudaGetSymbolAddress((void**)&p_k, g_k);
    cudaGetSymbolAddress((void**)&p_v, g_v);
    cudaGetSymbolAddress((void**)&p_posk, g_posk);
    cudaGetSymbolAddress((void**)&p_posq, g_posq);
    cudaGetSymbolAddress((void**)&p_c2p, g_c2p);
    cudaGetSymbolAddress((void**)&p_p2c, g_p2c);
    cudaGetSymbolAddress((void**)&p_ctx, g_ctx);
    cudaGetSymbolAddress((void**)&p_idx, g_idx);

    static bool attr_done = false;
    if (!attr_done) {
        cudaFuncSetAttribute(flash_tf32,
                             cudaFuncAttributeMaxDynamicSharedMemorySize, 73728);
        cudaFuncSetAttribute(mm_jobs_tf32,
                             cudaFuncAttributeMaxDynamicSharedMemorySize, MM_SMEM);
        attr_done = true;
    }

    build_idx_kernel<<<9, 256>>>(p_idx);
    ln_kernel<<<NK2, 256>>>(rel, ln_g, ln_b, p_re);

    // merged Q/K/V + pos-k/pos-q projections in one launch
    MMJobs jobs;
    jobs.j[0] = { hs,   Wq,  bq,  p_q,    NB * NS, NS  };
    jobs.j[1] = { hs,   Wk,  bk,  p_k,    NB * NS, NS  };
    jobs.j[2] = { hs,   Wv,  bv,  p_v,    NB * NS, NS  };
    jobs.j[3] = { p_re, Wpk, bpk, p_posk, NK2,     NK2 };
    jobs.j[4] = { p_re, Wpq, bpq, p_posq, NK2,     NK2 };
    mm_jobs_tf32<<<dim3(8, 32, 5), 256, MM_SMEM>>>(jobs);

    // c2p and p2c in one launch (bf16, pre-scaled by sqrt(1.5))
    nt64_pair_tf32<<<dim3(4, 8, 128), 256>>>(p_q, p_posk, p_k, p_posq, p_c2p, p_p2c);

    // fused attention
    flash_tf32<<<dim3(8, 64), 256, 73728>>>(p_q, p_k, p_v, p_c2p, p_p2c, p_idx, p_ctx);

    // out = ctx @ Wo + bo
    MMJobs jo;
    jo.j[0] = { p_ctx, Wo, bo, out, NB * NS, 0 };
    jo.j[1] = jo.j[0]; jo.j[2] = jo.j[0]; jo.j[3] = jo.j[0]; jo.j[4] = jo.j[0];
    mm_jobs_tf32<<<dim3(8, 32, 1), 256, MM_SMEM>>>(jo);
}

// round 15
// speedup vs baseline: 1.0916x; 1.0371x over previous
#include <cuda_runtime.h>
#include <cuda_bf16.h>
#include <math.h>

// Shapes (fixed by the problem)
#define NB 4
#define NH 16
#define NS 1024
#define ND 1024
#define HD 64
#define NK2 512   // 2 * BUCKETS
#define SPAN 256  // BUCKETS

// ---------------- scratch (device globals; no allocs allowed) ----------------
__device__ float g_re[NK2 * ND];
__device__ float g_q[(size_t)NB * NH * NS * HD];
__device__ float g_k[(size_t)NB * NH * NS * HD];
__device__ float g_v[(size_t)NB * NH * NS * HD];
__device__ float g_posk[NH * NK2 * HD];
__device__ float g_posq[NH * NK2 * HD];
__device__ __nv_bfloat16 g_c2p[(size_t)NB * NH * NS * NK2];  // pre-scaled sqrt(1.5)
__device__ __nv_bfloat16 g_p2c[(size_t)NB * NH * NS * NK2];  // pre-scaled sqrt(1.5)
__device__ float g_ctx[(size_t)NB * NS * ND];
__device__ int2  g_idx[2 * NS - 1];   // (idx1, idx2) per delta

// ---------------- helpers ----------------
__device__ __forceinline__ float f2tf(float x) {
    unsigned u;
    asm("cvt.rna.tf32.f32 %0, %1;" : "=r"(u) : "f"(x));
    return __uint_as_float(u);
}

__device__ __forceinline__ void mma_tf32(float* c, const float* a, const float* b) {
    asm volatile("mma.sync.aligned.m16n8k8.row.col.f32.tf32.tf32.f32 "
                 "{%0,%1,%2,%3}, {%4,%5,%6,%7}, {%8,%9}, {%0,%1,%2,%3};\n"
                 : "+f"(c[0]), "+f"(c[1]), "+f"(c[2]), "+f"(c[3])
                 : "r"(__float_as_uint(a[0])), "r"(__float_as_uint(a[1])),
                   "r"(__float_as_uint(a[2])), "r"(__float_as_uint(a[3])),
                   "r"(__float_as_uint(b[0])), "r"(__float_as_uint(b[1])));
}

__device__ __forceinline__ void cp16(float* dst, const float* src) {
    unsigned s = (unsigned)__cvta_generic_to_shared(dst);
    asm volatile("cp.async.cg.shared.global [%0], [%1], 16;" :: "r"(s), "l"(src));
}
__device__ __forceinline__ void cp_commit() { asm volatile("cp.async.commit_group;"); }
__device__ __forceinline__ void cp_wait0()  { asm volatile("cp.async.wait_group 0;"); }
__device__ __forceinline__ void cp_wait1()  { asm volatile("cp.async.wait_group 1;"); }
__device__ __forceinline__ void cp_wait2()  { asm volatile("cp.async.wait_group 2;"); }

// ---------------- bucket + index table (matches jax f32 semantics) -----------
__device__ __forceinline__ int bucketf(int rel) {
    const float mid = 128.0f;
    float signf = (rel > 0) ? 1.0f : (rel < 0 ? -1.0f : 0.0f);
    float abs_pos = (rel < 128 && rel > -128) ? 127.0f : fabsf((float)rel);
    float bucket;
    if (abs_pos <= mid) {
        bucket = (float)rel;
    } else {
        const float LOGC = 1.3843393289f;  // log(511/128) as f32
        float log_pos = ceilf(logf(abs_pos / mid) / LOGC * 127.0f) + mid;
        bucket = log_pos * signf;
    }
    return (int)bucket;
}

__global__ void build_idx_kernel(int2* idx) {
    int i = blockIdx.x * blockDim.x + threadIdx.x;
    if (i >= 2 * NS - 1) return;
    int rel = i - (NS - 1);          // delta = i - j
    int b1 = bucketf(rel);
    int b2 = bucketf(-rel);
    int2 v;
    v.x = min(max(b1 + SPAN, 0), 2 * SPAN - 1);
    v.y = min(max(SPAN - b2, 0), 2 * SPAN - 1);
    idx[i] = v;
}

// ---------------- LayerNorm for rel_emb [512,1024] ----------------
__global__ void ln_kernel(const float* __restrict__ x, const float* __restrict__ g,
                          const float* __restrict__ b, float* __restrict__ y) {
    int row = blockIdx.x;
    const float* xr = x + (size_t)row * ND;
    __shared__ float red[256];
    int tid = threadIdx.x;

    float s = 0.f;
    for (int i = tid; i < ND; i += 256) s += xr[i];
    red[tid] = s; __syncthreads();
    for (int o = 128; o > 0; o >>= 1) { if (tid < o) red[tid] += red[tid + o]; __syncthreads(); }
    float mu = red[0] * (1.0f / ND);
    __syncthreads();

    float v = 0.f;
    for (int i = tid; i < ND; i += 256) { float d = xr[i] - mu; v += d * d; }
    red[tid] = v; __syncthreads();
    for (int o = 128; o > 0; o >>= 1) { if (tid < o) red[tid] += red[tid + o]; __syncthreads(); }
    float var = red[0] * (1.0f / ND);
    float inv = 1.0f / sqrtf(var + 1e-5f);

    for (int i = tid; i < ND; i += 256)
        y[(size_t)row * ND + i] = (xr[i] - mu) * inv * g[i] + b[i];
}

// ============================================================================
// mm_jobs_tf32: up to 5 independent GEMMs (round-14 3-stage version; unchanged)
// ============================================================================
struct MMJob {
    const float* A; const float* W; const float* bias; float* C;
    int M; int splitR;
};
struct MMJobs { MMJob j[5]; };

#define MMA_ST 2560   // 128*20 floats per A stage
#define MMB_ST 2176   // 16*136 floats per B stage
#define MM_SMEM ((3 * (MMA_ST + MMB_ST)) * 4)   // 56832 bytes

__global__ __launch_bounds__(256, 2) void mm_jobs_tf32(MMJobs jobs)
{
    extern __shared__ float sm[];
    float* Asm = sm;
    float* Bsm = sm + 3 * MMA_ST;

    const MMJob jb = jobs.j[blockIdx.z];
    if (blockIdx.y * 128 >= jb.M) return;
    const float* A = jb.A; const float* W = jb.W;
    const float* bias = jb.bias; float* C = jb.C;
    const int splitR = jb.splitR;

    const int t = threadIdx.x, l = t & 31, w = t >> 5;
    const int gm = l >> 2, kq = l & 3;
    const int warpM = (w >> 1) * 32, warpN = (w & 1) * 64;
    const int rowBase = blockIdx.y * 128, colBase = blockIdx.x * 128;

    float acc[2][8][4];
#pragma unroll
    for (int i = 0; i < 2; ++i)
#pragma unroll
        for (int j = 0; j < 8; ++j)
#pragma unroll
            for (int e = 0; e < 4; ++e) acc[i][j][e] = 0.f;

    const int ar = t >> 1, ac = (t & 1) * 8;
    const int bk = t >> 4, bc = (t & 15) * 8;

#pragma unroll
    for (int p = 0; p < 2; ++p) {
        int k0 = p * 16;
        cp16(&Asm[p * MMA_ST + ar * 20 + ac],     A + (size_t)(rowBase + ar) * ND + k0 + ac);
        cp16(&Asm[p * MMA_ST + ar * 20 + ac + 4], A + (size_t)(rowBase + ar) * ND + k0 + ac + 4);
        cp16(&Bsm[p * MMB_ST + bk * 136 + bc],     W + (size_t)(k0 + bk) * ND + colBase + bc);
        cp16(&Bsm[p * MMB_ST + bk * 136 + bc + 4], W + (size_t)(k0 + bk) * ND + colBase + bc + 4);
        cp_commit();
    }

    int stC = 0, stI = 2;
    for (int c = 0; c < 64; ++c) {
        if (c + 2 < 64) {
            int k0 = (c + 2) * 16;
            cp16(&Asm[stI * MMA_ST + ar * 20 + ac],     A + (size_t)(rowBase + ar) * ND + k0 + ac);
            cp16(&Asm[stI * MMA_ST + ar * 20 + ac + 4], A + (size_t)(rowBase + ar) * ND + k0 + ac + 4);
            cp16(&Bsm[stI * MMB_ST + bk * 136 + bc],     W + (size_t)(k0 + bk) * ND + colBase + bc);
            cp16(&Bsm[stI * MMB_ST + bk * 136 + bc + 4], W + (size_t)(k0 + bk) * ND + colBase + bc + 4);
            cp_commit();
            cp_wait2();
        } else if (c + 1 < 64) {
            cp_wait1();
        } else {
            cp_wait0();
        }
        __syncthreads();

        const float* Ast = &Asm[stC * MMA_ST];
        const float* Bst = &Bsm[stC * MMB_ST];
#pragma unroll
        for (int ks = 0; ks < 2; ++ks) {
            const int k = ks * 8;
            float a[2][4], b[8][2];
#pragma unroll
            for (int mt = 0; mt < 2; ++mt) {
                int m = warpM + mt * 16 + gm;
                a[mt][0] = f2tf(Ast[m * 20 + k + kq]);
                a[mt][1] = f2tf(Ast[(m + 8) * 20 + k + kq]);
                a[mt][2] = f2tf(Ast[m * 20 + k + kq + 4]);
                a[mt][3] = f2tf(Ast[(m + 8) * 20 + k + kq + 4]);
            }
#pragma unroll
            for (int nt = 0; nt < 8; ++nt) {
                int n = warpN + nt * 8 + gm;
                b[nt][0] = f2tf(Bst[(k + kq) * 136 + n]);
                b[nt][1] = f2tf(Bst[(k + kq + 4) * 136 + n]);
            }
#pragma unroll
            for (int mt = 0; mt < 2; ++mt)
#pragma unroll
                for (int nt = 0; nt < 8; ++nt)
                    mma_tf32(acc[mt][nt], a[mt], b[nt]);
        }
        __syncthreads();

        stC = (stC == 2) ? 0 : stC + 1;
        stI = (stI == 2) ? 0 : stI + 1;
    }

#pragma unroll
    for (int mt = 0; mt < 2; ++mt) {
#pragma unroll
        for (int nt = 0; nt < 8; ++nt) {
            int r0 = rowBase + warpM + mt * 16 + gm;
            int c0 = colBase + warpN + nt * 8 + kq * 2;
#pragma unroll
            for (int half = 0; half < 2; ++half) {
                int r = r0 + half * 8;
                float v0 = acc[mt][nt][half * 2 + 0] + bias[c0];
                float v1 = acc[mt][nt][half * 2 + 1] + bias[c0 + 1];
                if (splitR == 0) {
                    *(float2*)&C[(size_t)r * ND + c0] = make_float2(v0, v1);
                } else {
                    v0 = f2tf(v0); v1 = f2tf(v1);
                    int h = c0 >> 6, d = c0 & 63;
                    int bb = r / splitR, rr = r - bb * splitR;
                    *(float2*)&C[(((size_t)bb * NH + h) * splitR + rr) * HD + d] =
                        make_float2(v0, v1);
                }
            }
        }
    }
}

// ============================================================================
// nt64_pair_tf32: c2p and p2c in one launch (round-13 structure; unchanged)
// ============================================================================
__global__ __launch_bounds__(256, 2) void nt64_pair_tf32(
    const float* __restrict__ q, const float* __restrict__ posk,
    const float* __restrict__ kk, const float* __restrict__ posq,
    __nv_bfloat16* __restrict__ c2p, __nv_bfloat16* __restrict__ p2c)
{
    __shared__ float As[2][128][20];
    __shared__ float Bs[2][128][20];

    const int t = threadIdx.x, l = t & 31, w = t >> 5;
    const int gm = l >> 2, kq = l & 3;
    const int warpM = (w >> 1) * 32, warpN = (w & 1) * 64;
    const int zz = blockIdx.z;
    const int batch = zz & 63;
    const int iBase = blockIdx.y * 128, jBase = blockIdx.x * 128;

    const float* Ab = ((zz < 64) ? q : kk) + (size_t)batch * NS * HD;
    const float* Bb = ((zz < 64) ? posk : posq) + (size_t)(batch & 15) * NK2 * HD;
    __nv_bfloat16* Cb = ((zz < 64) ? c2p : p2c) + (size_t)batch * NS * NK2;

    float acc[2][8][4];
#pragma unroll
    for (int i = 0; i < 2; ++i)
#pragma unroll
        for (int j = 0; j < 8; ++j)
#pragma unroll
            for (int e = 0; e < 4; ++e) acc[i][j][e] = 0.f;

    const int sr = t >> 1, sc = (t & 1) * 8;

    cp16(&As[0][sr][sc],     Ab + (size_t)(iBase + sr) * HD + sc);
    cp16(&As[0][sr][sc + 4], Ab + (size_t)(iBase + sr) * HD + sc + 4);
    cp16(&Bs[0][sr][sc],     Bb + (size_t)(jBase + sr) * HD + sc);
    cp16(&Bs[0][sr][sc + 4], Bb + (size_t)(jBase + sr) * HD + sc + 4);
    cp_commit();

#pragma unroll
    for (int c = 0; c < 4; ++c) {
        if (c + 1 < 4) {
            int d0 = (c + 1) * 16, s = (c + 1) & 1;
            cp16(&As[s][sr][sc],     Ab + (size_t)(iBase + sr) * HD + d0 + sc);
            cp16(&As[s][sr][sc + 4], Ab + (size_t)(iBase + sr) * HD + d0 + sc + 4);
            cp16(&Bs[s][sr][sc],     Bb + (size_t)(jBase + sr) * HD + d0 + sc);
            cp16(&Bs[s][sr][sc + 4], Bb + (size_t)(jBase + sr) * HD + d0 + sc + 4);
            cp_commit();
            cp_wait1();
        } else {
            cp_wait0();
        }
        __syncthreads();

        const int s = c & 1;
#pragma unroll
        for (int ks = 0; ks < 2; ++ks) {
            const int k = ks * 8;
            float a[2][4], b[8][2];
#pragma unroll
            for (int mt = 0; mt < 2; ++mt) {
                int m = warpM + mt * 16 + gm;
                a[mt][0] = As[s][m][k + kq];
                a[mt][1] = As[s][m + 8][k + kq];
                a[mt][2] = As[s][m][k + kq + 4];
                a[mt][3] = As[s][m + 8][k + kq + 4];
            }
#pragma unroll
            for (int nt = 0; nt < 8; ++nt) {
                int n = warpN + nt * 8 + gm;
                b[nt][0] = Bs[s][n][k + kq];
                b[nt][1] = Bs[s][n][k + kq + 4];
            }
#pragma unroll
            for (int mt = 0; mt < 2; ++mt)
#pragma unroll
                for (int nt = 0; nt < 8; ++nt)
                    mma_tf32(acc[mt][nt], a[mt], b[nt]);
        }
        __syncthreads();
    }

    const float sstore = 1.2247448713915890f;  // sqrt(1.5)
#pragma unroll
    for (int mt = 0; mt < 2; ++mt)
#pragma unroll
        for (int nt = 0; nt < 8; ++nt) {
            int r0 = iBase + warpM + mt * 16 + gm;
            int c0 = jBase + warpN + nt * 8 + kq * 2;
#pragma unroll
            for (int half = 0; half < 2; ++half) {
                __nv_bfloat162 pk;
                pk.x = __float2bfloat16(acc[mt][nt][half * 2 + 0] * sstore);
                pk.y = __float2bfloat16(acc[mt][nt][half * 2 + 1] * sstore);
                *(__nv_bfloat162*)&Cb[(size_t)(r0 + half * 8) * NK2 + c0] = pk;
            }
        }
}

// ============================================================================
// flash_tf32: fused scores + online softmax + PV.  64-row j-tiles (16 iters),
// smem 2*64*72*4 = 36864 B -> TWO CTAs/SM.  sc[8][4] halves register state.
// ============================================================================
#define FL_SMEM (2 * 64 * 72 * 4)

__global__ __launch_bounds__(256, 2) void flash_tf32(
    const float* __restrict__ q, const float* __restrict__ k,
    const float* __restrict__ v,
    const __nv_bfloat16* __restrict__ c2p, const __nv_bfloat16* __restrict__ p2c,
    const int2* __restrict__ idxt, float* __restrict__ ctx)
{
    extern __shared__ float smf[];
    float (*X0)[72] = (float(*)[72])smf;              // K tile 64x64 (Q staging at start)
    float (*X1)[72] = (float(*)[72])(smf + 64 * 72);  // V tile 64x64

    const int t = threadIdx.x, l = t & 31, w = t >> 5;
    const int gm = l >> 2, kq = l & 3;
    const int warpM = w * 16;
    const int z = blockIdx.y;
    const int bz = z >> 4, h = z & 15;
    const int iBase = blockIdx.x * 128;

    const float* Qb = q + (size_t)z * NS * HD;
    const float* Kb = k + (size_t)z * NS * HD;
    const float* Vb = v + (size_t)z * NS * HD;
    const __nv_bfloat16* c2pr = c2p + (size_t)z * NS * NK2;
    const __nv_bfloat16* p2cr = p2c + (size_t)z * NS * NK2;

    // 64-row tile staging: 4 threads per row, 16 floats each (4 cp16)
    const int sr = t >> 2, cb = (t & 3) * 16;
    const int i0 = iBase + warpM + gm;
    const int i1 = i0 + 8;

    // ---- load Q tile (128x64) through X0 in two halves, extract fragments ----
    float aq[8][4];
#pragma unroll
    for (int hv = 0; hv < 2; ++hv) {
#pragma unroll
        for (int i = 0; i < 4; ++i)
            cp16(&X0[sr][cb + i * 4],
                 Qb + (size_t)(iBase + hv * 64 + sr) * HD + cb + i * 4);
        cp_commit(); cp_wait0();
        __syncthreads();
        // warps whose rows are in this half grab their fragments
        if ((warpM >> 6) == hv) {
            int m = (warpM & 63) + gm;
#pragma unroll
            for (int ks = 0; ks < 8; ++ks) {
                int kk = ks * 8;
                aq[ks][0] = X0[m][kk + kq];
                aq[ks][1] = X0[m + 8][kk + kq];
                aq[ks][2] = X0[m][kk + kq + 4];
                aq[ks][3] = X0[m + 8][kk + kq + 4];
            }
        }
        __syncthreads();
    }

    // prefetch K(0) -> X0
#pragma unroll
    for (int i = 0; i < 4; ++i)
        cp16(&X0[sr][cb + i * 4], Kb + (size_t)sr * HD + cb + i * 4);
    cp_commit();   // pending: [K0]

    float m0 = -INFINITY, m1 = -INFINITY, l0 = 0.f, l1 = 0.f;   // raw units
    float o[8][4];
#pragma unroll
    for (int i = 0; i < 8; ++i)
#pragma unroll
        for (int e = 0; e < 4; ++e) o[i][e] = 0.f;

    const float inv192 = 0.07216878364870322f;  // 1/sqrt(64*3)
    const int srcA = (l & ~3) | (kq >> 1);
    const int srcB = srcA + 2;
    const bool odd = (kq & 1);

    for (int jt = 0; jt < 16; ++jt) {
        const int jBase = jt * 64;

        // issue V(jt) -> X1
#pragma unroll
        for (int i = 0; i < 4; ++i)
            cp16(&X1[sr][cb + i * 4], Vb + (size_t)(jBase + sr) * HD + cb + i * 4);
        cp_commit();        // pending: [K(jt), V(jt)]

        // ---- bias gathers initialize S (overlap with K(jt) in flight) ----
        float sc[8][4];
#pragma unroll
        for (int nt = 0; nt < 8; ++nt) {
#pragma unroll
            for (int e = 0; e < 4; ++e) {
                int i = (e < 2) ? i0 : i1;
                int j = jBase + nt * 8 + kq * 2 + (e & 1);
                int2 ip = idxt[i - j + (NS - 1)];
                sc[nt][e] = __bfloat162float(c2pr[(size_t)i * NK2 + ip.x])
                          + __bfloat162float(p2cr[(size_t)j * NK2 + ip.y]);
            }
        }

        cp_wait1();         // K(jt) resident
        __syncthreads();

        // ---- S += Q K^T (64 MMAs) ----
#pragma unroll
        for (int ks = 0; ks < 8; ++ks) {
            const int kk = ks * 8;
#pragma unroll
            for (int nt = 0; nt < 8; ++nt) {
                int n = nt * 8 + gm;
                float b[2];
                b[0] = X0[n][kk + kq];
                b[1] = X0[n][kk + kq + 4];
                mma_tf32(sc[nt], aq[ks], b);
            }
        }
        __syncthreads();

        // prefetch K(jt+1) -> X0 (overlaps softmax)
        if (jt + 1 < 16) {
#pragma unroll
            for (int i = 0; i < 4; ++i)
                cp16(&X0[sr][cb + i * 4],
                     Kb + (size_t)((jt + 1) * 64 + sr) * HD + cb + i * 4);
            cp_commit();
        }

        // ---- online softmax (raw units; inv192 folded into exp args) ----
        float tm0 = -INFINITY, tm1 = -INFINITY;
#pragma unroll
        for (int nt = 0; nt < 8; ++nt) {
            tm0 = fmaxf(tm0, fmaxf(sc[nt][0], sc[nt][1]));
            tm1 = fmaxf(tm1, fmaxf(sc[nt][2], sc[nt][3]));
        }
        tm0 = fmaxf(tm0, __shfl_xor_sync(0xffffffffu, tm0, 1));
        tm0 = fmaxf(tm0, __shfl_xor_sync(0xffffffffu, tm0, 2));
        tm1 = fmaxf(tm1, __shfl_xor_sync(0xffffffffu, tm1, 1));
        tm1 = fmaxf(tm1, __shfl_xor_sync(0xffffffffu, tm1, 2));

        float mn0 = fmaxf(m0, tm0), mn1 = fmaxf(m1, tm1);
        float fac0 = __expf((m0 - mn0) * inv192);
        float fac1 = __expf((m1 - mn1) * inv192);
        m0 = mn0; m1 = mn1;

        float s0 = 0.f, s1 = 0.f;
#pragma unroll
        for (int nt = 0; nt < 8; ++nt) {
            sc[nt][0] = f2tf(__expf((sc[nt][0] - mn0) * inv192));
            sc[nt][1] = f2tf(__expf((sc[nt][1] - mn0) * inv192));
            sc[nt][2] = f2tf(__expf((sc[nt][2] - mn1) * inv192));
            sc[nt][3] = f2tf(__expf((sc[nt][3] - mn1) * inv192));
            s0 += sc[nt][0] + sc[nt][1];
            s1 += sc[nt][2] + sc[nt][3];
        }
        s0 += __shfl_xor_sync(0xffffffffu, s0, 1);
        s0 += __shfl_xor_sync(0xffffffffu, s0, 2);
        s1 += __shfl_xor_sync(0xffffffffu, s1, 1);
        s1 += __shfl_xor_sync(0xffffffffu, s1, 2);
        l0 = l0 * fac0 + s0;
        l1 = l1 * fac1 + s1;

#pragma unroll
        for (int nt = 0; nt < 8; ++nt) {
            o[nt][0] *= fac0; o[nt][1] *= fac0;
            o[nt][2] *= fac1; o[nt][3] *= fac1;
        }

        // ---- wait V(jt), then PV (64 MMAs) ----
        if (jt + 1 < 16) cp_wait1(); else cp_wait0();
        __syncthreads();

#pragma unroll
        for (int ksg = 0; ksg < 8; ++ksg) {
            float e0 = __shfl_sync(0xffffffffu, sc[ksg][0], srcA);
            float e1 = __shfl_sync(0xffffffffu, sc[ksg][1], srcA);
            float e2 = __shfl_sync(0xffffffffu, sc[ksg][2], srcA);
            float e3 = __shfl_sync(0xffffffffu, sc[ksg][3], srcA);
            float f0 = __shfl_sync(0xffffffffu, sc[ksg][0], srcB);
            float f1 = __shfl_sync(0xffffffffu, sc[ksg][1], srcB);
            float f2 = __shfl_sync(0xffffffffu, sc[ksg][2], srcB);
            float f3 = __shfl_sync(0xffffffffu, sc[ksg][3], srcB);
            float pa[4];
            pa[0] = odd ? e1 : e0;
            pa[1] = odd ? e3 : e2;
            pa[2] = odd ? f1 : f0;
            pa[3] = odd ? f3 : f2;
#pragma unroll
            for (int nt = 0; nt < 8; ++nt) {
                int n = nt * 8 + gm;
                float b[2];
                b[0] = X1[ksg * 8 + kq][n];
                b[1] = X1[ksg * 8 + kq + 4][n];
                mma_tf32(o[nt], pa, b);
            }
        }
        __syncthreads();
    }

    // ---- normalize and store ctx ----
    float r0 = 1.0f / l0, r1 = 1.0f / l1;
#pragma unroll
    for (int nt = 0; nt < 8; ++nt) {
        int c0 = nt * 8 + kq * 2;
        *(float2*)&ctx[((size_t)bz * NS + i0) * ND + h * HD + c0] =
            make_float2(o[nt][0] * r0, o[nt][1] * r0);
        *(float2*)&ctx[((size_t)bz * NS + i1) * ND + h * HD + c0] =
            make_float2(o[nt][2] * r1, o[nt][3] * r1);
    }
}

// ---------------- launch ----------------
extern "C" void kernel_launch(void* const* d_in, const int* in_sizes, int n_in,
                              void* d_out, int out_size) {
    const float* hs    = (const float*)d_in[0];
    const float* Wq    = (const float*)d_in[1];
    const float* bq    = (const float*)d_in[2];
    const float* Wk    = (const float*)d_in[3];
    const float* bk    = (const float*)d_in[4];
    const float* Wv    = (const float*)d_in[5];
    const float* bv    = (const float*)d_in[6];
    const float* Wo    = (const float*)d_in[7];
    const float* bo    = (const float*)d_in[8];
    const float* rel   = (const float*)d_in[9];
    const float* ln_g  = (const float*)d_in[10];
    const float* ln_b  = (const float*)d_in[11];
    const float* Wpk   = (const float*)d_in[12];
    const float* bpk   = (const float*)d_in[13];
    const float* Wpq   = (const float*)d_in[14];
    const float* bpq   = (const float*)d_in[15];
    float* out = (float*)d_out;

    float *p_re, *p_q, *p_k, *p_v, *p_posk, *p_posq, *p_ctx;
    __nv_bfloat16 *p_c2p, *p_p2c;
    int2* p_idx;
    cudaGetSymbolAddress((void**)&p_re, g_re);
    cudaGetSymbolAddress((void**)&p_q, g_q);
    cudaGetSymbolAddress((void**)&p_k, g_k);
    cudaGetSymbolAddress((void**)&p_v, g_v);
    cudaGetSymbolAddress((void**)&p_posk, g_posk);
    cudaGetSymbolAddress((void**)&p_posq, g_posq);
    cudaGetSymbolAddress((void**)&p_c2p, g_c2p);
    cudaGetSymbolAddress((void**)&p_p2c, g_p2c);
    cudaGetSymbolAddress((void**)&p_ctx, g_ctx);
    cudaGetSymbolAddress((void**)&p_idx, g_idx);

    static bool attr_done = false;
    if (!attr_done) {
        cudaFuncSetAttribute(flash_tf32,
                             cudaFuncAttributeMaxDynamicSharedMemorySize, FL_SMEM);
        cudaFuncSetAttribute(mm_jobs_tf32,
                             cudaFuncAttributeMaxDynamicSharedMemorySize, MM_SMEM);
        attr_done = true;
    }

    build_idx_kernel<<<9, 256>>>(p_idx);
    ln_kernel<<<NK2, 256>>>(rel, ln_g, ln_b, p_re);

    // merged Q/K/V + pos-k/pos-q projections in one launch
    MMJobs jobs;
    jobs.j[0] = { hs,   Wq,  bq,  p_q,    NB * NS, NS  };
    jobs.j[1] = { hs,   Wk,  bk,  p_k,    NB * NS, NS  };
    jobs.j[2] = { hs,   Wv,  bv,  p_v,    NB * NS, NS  };
    jobs.j[3] = { p_re, Wpk, bpk, p_posk, NK2,     NK2 };
    jobs.j[4] = { p_re, Wpq, bpq, p_posq, NK2,     NK2 };
    mm_jobs_tf32<<<dim3(8, 32, 5), 256, MM_SMEM>>>(jobs);

    // c2p and p2c in one launch (bf16, pre-scaled by sqrt(1.5))
    nt64_pair_tf32<<<dim3(4, 8, 128), 256>>>(p_q, p_posk, p_k, p_posq, p_c2p, p_p2c);

    // fused attention (2 CTAs/SM)
    flash_tf32<<<dim3(8, 64), 256, FL_SMEM>>>(p_q, p_k, p_v, p_c2p, p_p2c, p_idx, p_ctx);

    // out = ctx @ Wo + bo
    MMJobs jo;
    jo.j[0] = { p_ctx, Wo, bo, out, NB * NS, 0 };
    jo.j[1] = jo.j[0]; jo.j[2] = jo.j[0]; jo.j[3] = jo.j[0]; jo.j[4] = jo.j[0];
    mm_jobs_tf32<<<dim3(8, 32, 1), 256, MM_SMEM>>>(jo);
}

// round 16
// speedup vs baseline: 1.1032x; 1.0106x over previous
#include <cuda_runtime.h>
#include <cuda_bf16.h>
#include <math.h>

// Shapes (fixed by the problem)
#define NB 4
#define NH 16
#define NS 1024
#define ND 1024
#define HD 64
#define NK2 512   // 2 * BUCKETS
#define SPAN 256  // BUCKETS

// ---------------- scratch (device globals; no allocs allowed) ----------------
__device__ float g_re[NK2 * ND];
__device__ float g_q[(size_t)NB * NH * NS * HD];
__device__ float g_k[(size_t)NB * NH * NS * HD];
__device__ float g_v[(size_t)NB * NH * NS * HD];
__device__ float g_posk[NH * NK2 * HD];
__device__ float g_posq[NH * NK2 * HD];
__device__ __nv_bfloat16 g_c2p[(size_t)NB * NH * NS * NK2];  // pre-scaled sqrt(1.5)
__device__ __nv_bfloat16 g_p2c[(size_t)NB * NH * NS * NK2];  // pre-scaled sqrt(1.5)
__device__ float g_ctx[(size_t)NB * NS * ND];
__device__ int2  g_idx[2 * NS - 1];   // (idx1, idx2) per delta

// ---------------- helpers ----------------
__device__ __forceinline__ float f2tf(float x) {
    unsigned u;
    asm("cvt.rna.tf32.f32 %0, %1;" : "=r"(u) : "f"(x));
    return __uint_as_float(u);
}

__device__ __forceinline__ void mma_tf32(float* c, const float* a, const float* b) {
    asm volatile("mma.sync.aligned.m16n8k8.row.col.f32.tf32.tf32.f32 "
                 "{%0,%1,%2,%3}, {%4,%5,%6,%7}, {%8,%9}, {%0,%1,%2,%3};\n"
                 : "+f"(c[0]), "+f"(c[1]), "+f"(c[2]), "+f"(c[3])
                 : "r"(__float_as_uint(a[0])), "r"(__float_as_uint(a[1])),
                   "r"(__float_as_uint(a[2])), "r"(__float_as_uint(a[3])),
                   "r"(__float_as_uint(b[0])), "r"(__float_as_uint(b[1])));
}

__device__ __forceinline__ void cp16(float* dst, const float* src) {
    unsigned s = (unsigned)__cvta_generic_to_shared(dst);
    asm volatile("cp.async.cg.shared.global [%0], [%1], 16;" :: "r"(s), "l"(src));
}
__device__ __forceinline__ void cp_commit() { asm volatile("cp.async.commit_group;"); }
__device__ __forceinline__ void cp_wait0()  { asm volatile("cp.async.wait_group 0;"); }
__device__ __forceinline__ void cp_wait1()  { asm volatile("cp.async.wait_group 1;"); }
__device__ __forceinline__ void cp_wait2()  { asm volatile("cp.async.wait_group 2;"); }
__device__ __forceinline__ void cp_wait3()  { asm volatile("cp.async.wait_group 3;"); }

// ---------------- bucket + index table (matches jax f32 semantics) -----------
__device__ __forceinline__ int bucketf(int rel) {
    const float mid = 128.0f;
    float signf = (rel > 0) ? 1.0f : (rel < 0 ? -1.0f : 0.0f);
    float abs_pos = (rel < 128 && rel > -128) ? 127.0f : fabsf((float)rel);
    float bucket;
    if (abs_pos <= mid) {
        bucket = (float)rel;
    } else {
        const float LOGC = 1.3843393289f;  // log(511/128) as f32
        float log_pos = ceilf(logf(abs_pos / mid) / LOGC * 127.0f) + mid;
        bucket = log_pos * signf;
    }
    return (int)bucket;
}

__global__ void build_idx_kernel(int2* idx) {
    int i = blockIdx.x * blockDim.x + threadIdx.x;
    if (i >= 2 * NS - 1) return;
    int rel = i - (NS - 1);          // delta = i - j
    int b1 = bucketf(rel);
    int b2 = bucketf(-rel);
    int2 v;
    v.x = min(max(b1 + SPAN, 0), 2 * SPAN - 1);
    v.y = min(max(SPAN - b2, 0), 2 * SPAN - 1);
    idx[i] = v;
}

// ---------------- LayerNorm for rel_emb [512,1024] ----------------
__global__ void ln_kernel(const float* __restrict__ x, const float* __restrict__ g,
                          const float* __restrict__ b, float* __restrict__ y) {
    int row = blockIdx.x;
    const float* xr = x + (size_t)row * ND;
    __shared__ float red[256];
    int tid = threadIdx.x;

    float s = 0.f;
    for (int i = tid; i < ND; i += 256) s += xr[i];
    red[tid] = s; __syncthreads();
    for (int o = 128; o > 0; o >>= 1) { if (tid < o) red[tid] += red[tid + o]; __syncthreads(); }
    float mu = red[0] * (1.0f / ND);
    __syncthreads();

    float v = 0.f;
    for (int i = tid; i < ND; i += 256) { float d = xr[i] - mu; v += d * d; }
    red[tid] = v; __syncthreads();
    for (int o = 128; o > 0; o >>= 1) { if (tid < o) red[tid] += red[tid + o]; __syncthreads(); }
    float var = red[0] * (1.0f / ND);
    float inv = 1.0f / sqrtf(var + 1e-5f);

    for (int i = tid; i < ND; i += 256)
        y[(size_t)row * ND + i] = (xr[i] - mu) * inv * g[i] + b[i];
}

// ============================================================================
// mm_jobs_tf32: up to 5 independent GEMMs (round-14 3-stage version; unchanged)
// ============================================================================
struct MMJob {
    const float* A; const float* W; const float* bias; float* C;
    int M; int splitR;
};
struct MMJobs { MMJob j[5]; };

#define MMA_ST 2560   // 128*20 floats per A stage
#define MMB_ST 2176   // 16*136 floats per B stage
#define MM_SMEM ((3 * (MMA_ST + MMB_ST)) * 4)   // 56832 bytes

__global__ __launch_bounds__(256, 2) void mm_jobs_tf32(MMJobs jobs)
{
    extern __shared__ float sm[];
    float* Asm = sm;
    float* Bsm = sm + 3 * MMA_ST;

    const MMJob jb = jobs.j[blockIdx.z];
    if (blockIdx.y * 128 >= jb.M) return;
    const float* A = jb.A; const float* W = jb.W;
    const float* bias = jb.bias; float* C = jb.C;
    const int splitR = jb.splitR;

    const int t = threadIdx.x, l = t & 31, w = t >> 5;
    const int gm = l >> 2, kq = l & 3;
    const int warpM = (w >> 1) * 32, warpN = (w & 1) * 64;
    const int rowBase = blockIdx.y * 128, colBase = blockIdx.x * 128;

    float acc[2][8][4];
#pragma unroll
    for (int i = 0; i < 2; ++i)
#pragma unroll
        for (int j = 0; j < 8; ++j)
#pragma unroll
            for (int e = 0; e < 4; ++e) acc[i][j][e] = 0.f;

    const int ar = t >> 1, ac = (t & 1) * 8;
    const int bk = t >> 4, bc = (t & 15) * 8;

#pragma unroll
    for (int p = 0; p < 2; ++p) {
        int k0 = p * 16;
        cp16(&Asm[p * MMA_ST + ar * 20 + ac],     A + (size_t)(rowBase + ar) * ND + k0 + ac);
        cp16(&Asm[p * MMA_ST + ar * 20 + ac + 4], A + (size_t)(rowBase + ar) * ND + k0 + ac + 4);
        cp16(&Bsm[p * MMB_ST + bk * 136 + bc],     W + (size_t)(k0 + bk) * ND + colBase + bc);
        cp16(&Bsm[p * MMB_ST + bk * 136 + bc + 4], W + (size_t)(k0 + bk) * ND + colBase + bc + 4);
        cp_commit();
    }

    int stC = 0, stI = 2;
    for (int c = 0; c < 64; ++c) {
        if (c + 2 < 64) {
            int k0 = (c + 2) * 16;
            cp16(&Asm[stI * MMA_ST + ar * 20 + ac],     A + (size_t)(rowBase + ar) * ND + k0 + ac);
            cp16(&Asm[stI * MMA_ST + ar * 20 + ac + 4], A + (size_t)(rowBase + ar) * ND + k0 + ac + 4);
            cp16(&Bsm[stI * MMB_ST + bk * 136 + bc],     W + (size_t)(k0 + bk) * ND + colBase + bc);
            cp16(&Bsm[stI * MMB_ST + bk * 136 + bc + 4], W + (size_t)(k0 + bk) * ND + colBase + bc + 4);
            cp_commit();
            cp_wait2();
        } else if (c + 1 < 64) {
            cp_wait1();
        } else {
            cp_wait0();
        }
        __syncthreads();

        const float* Ast = &Asm[stC * MMA_ST];
        const float* Bst = &Bsm[stC * MMB_ST];
#pragma unroll
        for (int ks = 0; ks < 2; ++ks) {
            const int k = ks * 8;
            float a[2][4], b[8][2];
#pragma unroll
            for (int mt = 0; mt < 2; ++mt) {
                int m = warpM + mt * 16 + gm;
                a[mt][0] = f2tf(Ast[m * 20 + k + kq]);
                a[mt][1] = f2tf(Ast[(m + 8) * 20 + k + kq]);
                a[mt][2] = f2tf(Ast[m * 20 + k + kq + 4]);
                a[mt][3] = f2tf(Ast[(m + 8) * 20 + k + kq + 4]);
            }
#pragma unroll
            for (int nt = 0; nt < 8; ++nt) {
                int n = warpN + nt * 8 + gm;
                b[nt][0] = f2tf(Bst[(k + kq) * 136 + n]);
                b[nt][1] = f2tf(Bst[(k + kq + 4) * 136 + n]);
            }
#pragma unroll
            for (int mt = 0; mt < 2; ++mt)
#pragma unroll
                for (int nt = 0; nt < 8; ++nt)
                    mma_tf32(acc[mt][nt], a[mt], b[nt]);
        }
        __syncthreads();

        stC = (stC == 2) ? 0 : stC + 1;
        stI = (stI == 2) ? 0 : stI + 1;
    }

#pragma unroll
    for (int mt = 0; mt < 2; ++mt) {
#pragma unroll
        for (int nt = 0; nt < 8; ++nt) {
            int r0 = rowBase + warpM + mt * 16 + gm;
            int c0 = colBase + warpN + nt * 8 + kq * 2;
#pragma unroll
            for (int half = 0; half < 2; ++half) {
                int r = r0 + half * 8;
                float v0 = acc[mt][nt][half * 2 + 0] + bias[c0];
                float v1 = acc[mt][nt][half * 2 + 1] + bias[c0 + 1];
                if (splitR == 0) {
                    *(float2*)&C[(size_t)r * ND + c0] = make_float2(v0, v1);
                } else {
                    v0 = f2tf(v0); v1 = f2tf(v1);
                    int h = c0 >> 6, d = c0 & 63;
                    int bb = r / splitR, rr = r - bb * splitR;
                    *(float2*)&C[(((size_t)bb * NH + h) * splitR + rr) * HD + d] =
                        make_float2(v0, v1);
                }
            }
        }
    }
}

// ============================================================================
// nt64_pair_tf32: c2p and p2c in one launch.
// 4-STAGE progressive pipeline with the PROVEN 2-threads/row staging:
// all 4 K-16 chunks issued up-front (4 commit groups), wait 3/2/1/0 + one
// sync per chunk. Stages written once -> no WAR hazards, 4 barriers total.
// Dynamic smem 81920 B; 2 CTAs/SM.
// ============================================================================
#define NT_ST 2560   // 128*20 floats per stage (per matrix)
#define NT_SMEM ((4 * NT_ST * 2) * 4)   // 81920 bytes

__global__ __launch_bounds__(256, 2) void nt64_pair_tf32(
    const float* __restrict__ q, const float* __restrict__ posk,
    const float* __restrict__ kk, const float* __restrict__ posq,
    __nv_bfloat16* __restrict__ c2p, __nv_bfloat16* __restrict__ p2c)
{
    extern __shared__ float sm[];
    float* Asm = sm;                  // 4 stages of [128][20]
    float* Bsm = sm + 4 * NT_ST;      // 4 stages of [128][20]

    const int t = threadIdx.x, l = t & 31, w = t >> 5;
    const int gm = l >> 2, kq = l & 3;
    const int warpM = (w >> 1) * 32, warpN = (w & 1) * 64;
    const int zz = blockIdx.z;
    const int batch = zz & 63;
    const int iBase = blockIdx.y * 128, jBase = blockIdx.x * 128;

    const float* Ab = ((zz < 64) ? q : kk) + (size_t)batch * NS * HD;
    const float* Bb = ((zz < 64) ? posk : posq) + (size_t)(batch & 15) * NK2 * HD;
    __nv_bfloat16* Cb = ((zz < 64) ? c2p : p2c) + (size_t)batch * NS * NK2;

    const int sr = t >> 1, sc = (t & 1) * 8;

    // issue all 4 chunks up-front, one commit group each
#pragma unroll
    for (int c = 0; c < 4; ++c) {
        int d0 = c * 16;
        cp16(&Asm[c * NT_ST + sr * 20 + sc],     Ab + (size_t)(iBase + sr) * HD + d0 + sc);
        cp16(&Asm[c * NT_ST + sr * 20 + sc + 4], Ab + (size_t)(iBase + sr) * HD + d0 + sc + 4);
        cp16(&Bsm[c * NT_ST + sr * 20 + sc],     Bb + (size_t)(jBase + sr) * HD + d0 + sc);
        cp16(&Bsm[c * NT_ST + sr * 20 + sc + 4], Bb + (size_t)(jBase + sr) * HD + d0 + sc + 4);
        cp_commit();
    }

    float acc[2][8][4];
#pragma unroll
    for (int i = 0; i < 2; ++i)
#pragma unroll
        for (int j = 0; j < 8; ++j)
#pragma unroll
            for (int e = 0; e < 4; ++e) acc[i][j][e] = 0.f;

#pragma unroll
    for (int c = 0; c < 4; ++c) {
        if (c == 0) cp_wait3();
        else if (c == 1) cp_wait2();
        else if (c == 2) cp_wait1();
        else cp_wait0();
        __syncthreads();

        const float* Ast = &Asm[c * NT_ST];
        const float* Bst = &Bsm[c * NT_ST];
#pragma unroll
        for (int ks = 0; ks < 2; ++ks) {
            const int k = ks * 8;
            float a[2][4], b[8][2];
#pragma unroll
            for (int mt = 0; mt < 2; ++mt) {
                int m = warpM + mt * 16 + gm;
                a[mt][0] = Ast[m * 20 + k + kq];
                a[mt][1] = Ast[(m + 8) * 20 + k + kq];
                a[mt][2] = Ast[m * 20 + k + kq + 4];
                a[mt][3] = Ast[(m + 8) * 20 + k + kq + 4];
            }
#pragma unroll
            for (int nt = 0; nt < 8; ++nt) {
                int n = warpN + nt * 8 + gm;
                b[nt][0] = Bst[n * 20 + k + kq];
                b[nt][1] = Bst[n * 20 + k + kq + 4];
            }
#pragma unroll
            for (int mt = 0; mt < 2; ++mt)
#pragma unroll
                for (int nt = 0; nt < 8; ++nt)
                    mma_tf32(acc[mt][nt], a[mt], b[nt]);
        }
    }

    const float sstore = 1.2247448713915890f;  // sqrt(1.5)
#pragma unroll
    for (int mt = 0; mt < 2; ++mt)
#pragma unroll
        for (int nt = 0; nt < 8; ++nt) {
            int r0 = iBase + warpM + mt * 16 + gm;
            int c0 = jBase + warpN + nt * 8 + kq * 2;
#pragma unroll
            for (int half = 0; half < 2; ++half) {
                __nv_bfloat162 pk;
                pk.x = __float2bfloat16(acc[mt][nt][half * 2 + 0] * sstore);
                pk.y = __float2bfloat16(acc[mt][nt][half * 2 + 1] * sstore);
                *(__nv_bfloat162*)&Cb[(size_t)(r0 + half * 8) * NK2 + c0] = pk;
            }
        }
}

// ============================================================================
// flash_tf32: fused scores + online softmax + PV (round-15 64-row j-tiles,
// 2 CTAs/SM; unchanged)
// ============================================================================
#define FL_SMEM (2 * 64 * 72 * 4)

__global__ __launch_bounds__(256, 2) void flash_tf32(
    const float* __restrict__ q, const float* __restrict__ k,
    const float* __restrict__ v,
    const __nv_bfloat16* __restrict__ c2p, const __nv_bfloat16* __restrict__ p2c,
    const int2* __restrict__ idxt, float* __restrict__ ctx)
{
    extern __shared__ float smf[];
    float (*X0)[72] = (float(*)[72])smf;
    float (*X1)[72] = (float(*)[72])(smf + 64 * 72);

    const int t = threadIdx.x, l = t & 31, w = t >> 5;
    const int gm = l >> 2, kq = l & 3;
    const int warpM = w * 16;
    const int z = blockIdx.y;
    const int bz = z >> 4, h = z & 15;
    const int iBase = blockIdx.x * 128;

    const float* Qb = q + (size_t)z * NS * HD;
    const float* Kb = k + (size_t)z * NS * HD;
    const float* Vb = v + (size_t)z * NS * HD;
    const __nv_bfloat16* c2pr = c2p + (size_t)z * NS * NK2;
    const __nv_bfloat16* p2cr = p2c + (size_t)z * NS * NK2;

    const int sr = t >> 2, cb = (t & 3) * 16;
    const int i0 = iBase + warpM + gm;
    const int i1 = i0 + 8;

    // ---- load Q tile (128x64) through X0 in two halves, extract fragments ----
    float aq[8][4];
#pragma unroll
    for (int hv = 0; hv < 2; ++hv) {
#pragma unroll
        for (int i = 0; i < 4; ++i)
            cp16(&X0[sr][cb + i * 4],
                 Qb + (size_t)(iBase + hv * 64 + sr) * HD + cb + i * 4);
        cp_commit(); cp_wait0();
        __syncthreads();
        if ((warpM >> 6) == hv) {
            int m = (warpM & 63) + gm;
#pragma unroll
            for (int ks = 0; ks < 8; ++ks) {
                int kk = ks * 8;
                aq[ks][0] = X0[m][kk + kq];
                aq[ks][1] = X0[m + 8][kk + kq];
                aq[ks][2] = X0[m][kk + kq + 4];
                aq[ks][3] = X0[m + 8][kk + kq + 4];
            }
        }
        __syncthreads();
    }

    // prefetch K(0) -> X0
#pragma unroll
    for (int i = 0; i < 4; ++i)
        cp16(&X0[sr][cb + i * 4], Kb + (size_t)sr * HD + cb + i * 4);
    cp_commit();   // pending: [K0]

    float m0 = -INFINITY, m1 = -INFINITY, l0 = 0.f, l1 = 0.f;   // raw units
    float o[8][4];
#pragma unroll
    for (int i = 0; i < 8; ++i)
#pragma unroll
        for (int e = 0; e < 4; ++e) o[i][e] = 0.f;

    const float inv192 = 0.07216878364870322f;  // 1/sqrt(64*3)
    const int srcA = (l & ~3) | (kq >> 1);
    const int srcB = srcA + 2;
    const bool odd = (kq & 1);

    for (int jt = 0; jt < 16; ++jt) {
        const int jBase = jt * 64;

        // issue V(jt) -> X1
#pragma unroll
        for (int i = 0; i < 4; ++i)
            cp16(&X1[sr][cb + i * 4], Vb + (size_t)(jBase + sr) * HD + cb + i * 4);
        cp_commit();        // pending: [K(jt), V(jt)]

        // ---- bias gathers initialize S (overlap with K(jt) in flight) ----
        float sc[8][4];
#pragma unroll
        for (int nt = 0; nt < 8; ++nt) {
#pragma unroll
            for (int e = 0; e < 4; ++e) {
                int i = (e < 2) ? i0 : i1;
                int j = jBase + nt * 8 + kq * 2 + (e & 1);
                int2 ip = idxt[i - j + (NS - 1)];
                sc[nt][e] = __bfloat162float(c2pr[(size_t)i * NK2 + ip.x])
                          + __bfloat162float(p2cr[(size_t)j * NK2 + ip.y]);
            }
        }

        cp_wait1();         // K(jt) resident
        __syncthreads();

        // ---- S += Q K^T (64 MMAs) ----
#pragma unroll
        for (int ks = 0; ks < 8; ++ks) {
            const int kk = ks * 8;
#pragma unroll
            for (int nt = 0; nt < 8; ++nt) {
                int n = nt * 8 + gm;
                float b[2];
                b[0] = X0[n][kk + kq];
                b[1] = X0[n][kk + kq + 4];
                mma_tf32(sc[nt], aq[ks], b);
            }
        }
        __syncthreads();

        // prefetch K(jt+1) -> X0 (overlaps softmax)
        if (jt + 1 < 16) {
#pragma unroll
            for (int i = 0; i < 4; ++i)
                cp16(&X0[sr][cb + i * 4],
                     Kb + (size_t)((jt + 1) * 64 + sr) * HD + cb + i * 4);
            cp_commit();
        }

        // ---- online softmax ----
        float tm0 = -INFINITY, tm1 = -INFINITY;
#pragma unroll
        for (int nt = 0; nt < 8; ++nt) {
            tm0 = fmaxf(tm0, fmaxf(sc[nt][0], sc[nt][1]));
            tm1 = fmaxf(tm1, fmaxf(sc[nt][2], sc[nt][3]));
        }
        tm0 = fmaxf(tm0, __shfl_xor_sync(0xffffffffu, tm0, 1));
        tm0 = fmaxf(tm0, __shfl_xor_sync(0xffffffffu, tm0, 2));
        tm1 = fmaxf(tm1, __shfl_xor_sync(0xffffffffu, tm1, 1));
        tm1 = fmaxf(tm1, __shfl_xor_sync(0xffffffffu, tm1, 2));

        float mn0 = fmaxf(m0, tm0), mn1 = fmaxf(m1, tm1);
        float fac0 = __expf((m0 - mn0) * inv192);
        float fac1 = __expf((m1 - mn1) * inv192);
        m0 = mn0; m1 = mn1;

        float s0 = 0.f, s1 = 0.f;
#pragma unroll
        for (int nt = 0; nt < 8; ++nt) {
            sc[nt][0] = f2tf(__expf((sc[nt][0] - mn0) * inv192));
            sc[nt][1] = f2tf(__expf((sc[nt][1] - mn0) * inv192));
            sc[nt][2] = f2tf(__expf((sc[nt][2] - mn1) * inv192));
            sc[nt][3] = f2tf(__expf((sc[nt][3] - mn1) * inv192));
            s0 += sc[nt][0] + sc[nt][1];
            s1 += sc[nt][2] + sc[nt][3];
        }
        s0 += __shfl_xor_sync(0xffffffffu, s0, 1);
        s0 += __shfl_xor_sync(0xffffffffu, s0, 2);
        s1 += __shfl_xor_sync(0xffffffffu, s1, 1);
        s1 += __shfl_xor_sync(0xffffffffu, s1, 2);
        l0 = l0 * fac0 + s0;
        l1 = l1 * fac1 + s1;

#pragma unroll
        for (int nt = 0; nt < 8; ++nt) {
            o[nt][0] *= fac0; o[nt][1] *= fac0;
            o[nt][2] *= fac1; o[nt][3] *= fac1;
        }

        // ---- wait V(jt), then PV (64 MMAs) ----
        if (jt + 1 < 16) cp_wait1(); else cp_wait0();
        __syncthreads();

#pragma unroll
        for (int ksg = 0; ksg < 8; ++ksg) {
            float e0 = __shfl_sync(0xffffffffu, sc[ksg][0], srcA);
            float e1 = __shfl_sync(0xffffffffu, sc[ksg][1], srcA);
            float e2 = __shfl_sync(0xffffffffu, sc[ksg][2], srcA);
            float e3 = __shfl_sync(0xffffffffu, sc[ksg][3], srcA);
            float f0 = __shfl_sync(0xffffffffu, sc[ksg][0], srcB);
            float f1 = __shfl_sync(0xffffffffu, sc[ksg][1], srcB);
            float f2 = __shfl_sync(0xffffffffu, sc[ksg][2], srcB);
            float f3 = __shfl_sync(0xffffffffu, sc[ksg][3], srcB);
            float pa[4];
            pa[0] = odd ? e1 : e0;
            pa[1] = odd ? e3 : e2;
            pa[2] = odd ? f1 : f0;
            pa[3] = odd ? f3 : f2;
#pragma unroll
            for (int nt = 0; nt < 8; ++nt) {
                int n = nt * 8 + gm;
                float b[2];
                b[0] = X1[ksg * 8 + kq][n];
                b[1] = X1[ksg * 8 + kq + 4][n];
                mma_tf32(o[nt], pa, b);
            }
        }
        __syncthreads();
    }

    // ---- normalize and store ctx ----
    float r0 = 1.0f / l0, r1 = 1.0f / l1;
#pragma unroll
    for (int nt = 0; nt < 8; ++nt) {
        int c0 = nt * 8 + kq * 2;
        *(float2*)&ctx[((size_t)bz * NS + i0) * ND + h * HD + c0] =
            make_float2(o[nt][0] * r0, o[nt][1] * r0);
        *(float2*)&ctx[((size_t)bz * NS + i1) * ND + h * HD + c0] =
            make_float2(o[nt][2] * r1, o[nt][3] * r1);
    }
}

// ---------------- launch ----------------
extern "C" void kernel_launch(void* const* d_in, const int* in_sizes, int n_in,
                              void* d_out, int out_size) {
    const float* hs    = (const float*)d_in[0];
    const float* Wq    = (const float*)d_in[1];
    const float* bq    = (const float*)d_in[2];
    const float* Wk    = (const float*)d_in[3];
    const float* bk    = (const float*)d_in[4];
    const float* Wv    = (const float*)d_in[5];
    const float* bv    = (const float*)d_in[6];
    const float* Wo    = (const float*)d_in[7];
    const float* bo    = (const float*)d_in[8];
    const float* rel   = (const float*)d_in[9];
    const float* ln_g  = (const float*)d_in[10];
    const float* ln_b  = (const float*)d_in[11];
    const float* Wpk   = (const float*)d_in[12];
    const float* bpk   = (const float*)d_in[13];
    const float* Wpq   = (const float*)d_in[14];
    const float* bpq   = (const float*)d_in[15];
    float* out = (float*)d_out;

    float *p_re, *p_q, *p_k, *p_v, *p_posk, *p_posq, *p_ctx;
    __nv_bfloat16 *p_c2p, *p_p2c;
    int2* p_idx;
    cudaGetSymbolAddress((void**)&p_re, g_re);
    cudaGetSymbolAddress((void**)&p_q, g_q);
    cudaGetSymbolAddress((void**)&p_k, g_k);
    cudaGetSymbolAddress((void**)&p_v, g_v);
    cudaGetSymbolAddress((void**)&p_posk, g_posk);
    cudaGetSymbolAddress((void**)&p_posq, g_posq);
    cudaGetSymbolAddress((void**)&p_c2p, g_c2p);
    cudaGetSymbolAddress((void**)&p_p2c, g_p2c);
    cudaGetSymbolAddress((void**)&p_ctx, g_ctx);
    cudaGetSymbolAddress((void**)&p_idx, g_idx);

    static bool attr_done = false;
    if (!attr_done) {
        cudaFuncSetAttribute(flash_tf32,
                             cudaFuncAttributeMaxDynamicSharedMemorySize, FL_SMEM);
        cudaFuncSetAttribute(mm_jobs_tf32,
                             cudaFuncAttributeMaxDynamicSharedMemorySize, MM_SMEM);
        cudaFuncSetAttribute(nt64_pair_tf32,
                             cudaFuncAttributeMaxDynamicSharedMemorySize, NT_SMEM);
        attr_done = true;
    }

    build_idx_kernel<<<9, 256>>>(p_idx);
    ln_kernel<<<NK2, 256>>>(rel, ln_g, ln_b, p_re);

    // merged Q/K/V + pos-k/pos-q projections in one launch
    MMJobs jobs;
    jobs.j[0] = { hs,   Wq,  bq,  p_q,    NB * NS, NS  };
    jobs.j[1] = { hs,   Wk,  bk,  p_k,    NB * NS, NS  };
    jobs.j[2] = { hs,   Wv,  bv,  p_v,    NB * NS, NS  };
    jobs.j[3] = { p_re, Wpk, bpk, p_posk, NK2,     NK2 };
    jobs.j[4] = { p_re, Wpq, bpq, p_posq, NK2,     NK2 };
    mm_jobs_tf32<<<dim3(8, 32, 5), 256, MM_SMEM>>>(jobs);

    // c2p and p2c in one launch (bf16, pre-scaled by sqrt(1.5))
    nt64_pair_tf32<<<dim3(4, 8, 128), 256, NT_SMEM>>>(p_q, p_posk, p_k, p_posq, p_c2p, p_p2c);

    // fused attention (2 CTAs/SM)
    flash_tf32<<<dim3(8, 64), 256, FL_SMEM>>>(p_q, p_k, p_v, p_c2p, p_p2c, p_idx, p_ctx);

    // out = ctx @ Wo + bo
    MMJobs jo;
    jo.j[0] = { p_ctx, Wo, bo, out, NB * NS, 0 };
    jo.j[1] = jo.j[0]; jo.j[2] = jo.j[0]; jo.j[3] = jo.j[0]; jo.j[4] = jo.j[0];
    mm_jobs_tf32<<<dim3(8, 32, 1), 256, MM_SMEM>>>(jo);
}

// round 17
// speedup vs baseline: 1.1067x; 1.0032x over previous
#include <cuda_runtime.h>
#include <cuda_bf16.h>
#include <math.h>

// Shapes (fixed by the problem)
#define NB 4
#define NH 16
#define NS 1024
#define ND 1024
#define HD 64
#define NK2 512   // 2 * BUCKETS
#define SPAN 256  // BUCKETS

// ---------------- scratch (device globals; no allocs allowed) ----------------
__device__ float g_re[NK2 * ND];
__device__ float g_q[(size_t)NB * NH * NS * HD];
__device__ float g_k[(size_t)NB * NH * NS * HD];
__device__ float g_v[(size_t)NB * NH * NS * HD];
__device__ float g_posk[NH * NK2 * HD];
__device__ float g_posq[NH * NK2 * HD];
__device__ __nv_bfloat16 g_c2p[(size_t)NB * NH * NS * NK2];  // pre-scaled sqrt(1.5)
__device__ __nv_bfloat16 g_p2c[(size_t)NB * NH * NS * NK2];  // pre-scaled sqrt(1.5)
__device__ float g_ctx[(size_t)NB * NS * ND];
__device__ int2  g_idx[2 * NS - 1];   // (idx1, idx2) per delta

// ---------------- helpers ----------------
__device__ __forceinline__ float f2tf(float x) {
    unsigned u;
    asm("cvt.rna.tf32.f32 %0, %1;" : "=r"(u) : "f"(x));
    return __uint_as_float(u);
}

__device__ __forceinline__ void mma_tf32(float* c, const float* a, const float* b) {
    asm volatile("mma.sync.aligned.m16n8k8.row.col.f32.tf32.tf32.f32 "
                 "{%0,%1,%2,%3}, {%4,%5,%6,%7}, {%8,%9}, {%0,%1,%2,%3};\n"
                 : "+f"(c[0]), "+f"(c[1]), "+f"(c[2]), "+f"(c[3])
                 : "r"(__float_as_uint(a[0])), "r"(__float_as_uint(a[1])),
                   "r"(__float_as_uint(a[2])), "r"(__float_as_uint(a[3])),
                   "r"(__float_as_uint(b[0])), "r"(__float_as_uint(b[1])));
}

__device__ __forceinline__ void cp16(float* dst, const float* src) {
    unsigned s = (unsigned)__cvta_generic_to_shared(dst);
    asm volatile("cp.async.cg.shared.global [%0], [%1], 16;" :: "r"(s), "l"(src));
}
__device__ __forceinline__ void cp_commit() { asm volatile("cp.async.commit_group;"); }
__device__ __forceinline__ void cp_wait0()  { asm volatile("cp.async.wait_group 0;"); }
__device__ __forceinline__ void cp_wait1()  { asm volatile("cp.async.wait_group 1;"); }
__device__ __forceinline__ void cp_wait2()  { asm volatile("cp.async.wait_group 2;"); }
__device__ __forceinline__ void cp_wait3()  { asm volatile("cp.async.wait_group 3;"); }

// ---------------- bucket + index table (matches jax f32 semantics) -----------
__device__ __forceinline__ int bucketf(int rel) {
    const float mid = 128.0f;
    float signf = (rel > 0) ? 1.0f : (rel < 0 ? -1.0f : 0.0f);
    float abs_pos = (rel < 128 && rel > -128) ? 127.0f : fabsf((float)rel);
    float bucket;
    if (abs_pos <= mid) {
        bucket = (float)rel;
    } else {
        const float LOGC = 1.3843393289f;  // log(511/128) as f32
        float log_pos = ceilf(logf(abs_pos / mid) / LOGC * 127.0f) + mid;
        bucket = log_pos * signf;
    }
    return (int)bucket;
}

__global__ void build_idx_kernel(int2* idx) {
    int i = blockIdx.x * blockDim.x + threadIdx.x;
    if (i >= 2 * NS - 1) return;
    int rel = i - (NS - 1);          // delta = i - j
    int b1 = bucketf(rel);
    int b2 = bucketf(-rel);
    int2 v;
    v.x = min(max(b1 + SPAN, 0), 2 * SPAN - 1);
    v.y = min(max(SPAN - b2, 0), 2 * SPAN - 1);
    idx[i] = v;
}

// ---------------- LayerNorm for rel_emb [512,1024] ----------------
__global__ void ln_kernel(const float* __restrict__ x, const float* __restrict__ g,
                          const float* __restrict__ b, float* __restrict__ y) {
    int row = blockIdx.x;
    const float* xr = x + (size_t)row * ND;
    __shared__ float red[256];
    int tid = threadIdx.x;

    float s = 0.f;
    for (int i = tid; i < ND; i += 256) s += xr[i];
    red[tid] = s; __syncthreads();
    for (int o = 128; o > 0; o >>= 1) { if (tid < o) red[tid] += red[tid + o]; __syncthreads(); }
    float mu = red[0] * (1.0f / ND);
    __syncthreads();

    float v = 0.f;
    for (int i = tid; i < ND; i += 256) { float d = xr[i] - mu; v += d * d; }
    red[tid] = v; __syncthreads();
    for (int o = 128; o > 0; o >>= 1) { if (tid < o) red[tid] += red[tid + o]; __syncthreads(); }
    float var = red[0] * (1.0f / ND);
    float inv = 1.0f / sqrtf(var + 1e-5f);

    for (int i = tid; i < ND; i += 256)
        y[(size_t)row * ND + i] = (xr[i] - mu) * inv * g[i] + b[i];
}

// ============================================================================
// mm_jobs_tf32: up to 5 independent GEMMs (round-14 3-stage version; unchanged)
// ============================================================================
struct MMJob {
    const float* A; const float* W; const float* bias; float* C;
    int M; int splitR;
};
struct MMJobs { MMJob j[5]; };

#define MMA_ST 2560   // 128*20 floats per A stage
#define MMB_ST 2176   // 16*136 floats per B stage
#define MM_SMEM ((3 * (MMA_ST + MMB_ST)) * 4)   // 56832 bytes

__global__ __launch_bounds__(256, 2) void mm_jobs_tf32(MMJobs jobs)
{
    extern __shared__ float sm[];
    float* Asm = sm;
    float* Bsm = sm + 3 * MMA_ST;

    const MMJob jb = jobs.j[blockIdx.z];
    if (blockIdx.y * 128 >= jb.M) return;
    const float* A = jb.A; const float* W = jb.W;
    const float* bias = jb.bias; float* C = jb.C;
    const int splitR = jb.splitR;

    const int t = threadIdx.x, l = t & 31, w = t >> 5;
    const int gm = l >> 2, kq = l & 3;
    const int warpM = (w >> 1) * 32, warpN = (w & 1) * 64;
    const int rowBase = blockIdx.y * 128, colBase = blockIdx.x * 128;

    float acc[2][8][4];
#pragma unroll
    for (int i = 0; i < 2; ++i)
#pragma unroll
        for (int j = 0; j < 8; ++j)
#pragma unroll
            for (int e = 0; e < 4; ++e) acc[i][j][e] = 0.f;

    const int ar = t >> 1, ac = (t & 1) * 8;
    const int bk = t >> 4, bc = (t & 15) * 8;

#pragma unroll
    for (int p = 0; p < 2; ++p) {
        int k0 = p * 16;
        cp16(&Asm[p * MMA_ST + ar * 20 + ac],     A + (size_t)(rowBase + ar) * ND + k0 + ac);
        cp16(&Asm[p * MMA_ST + ar * 20 + ac + 4], A + (size_t)(rowBase + ar) * ND + k0 + ac + 4);
        cp16(&Bsm[p * MMB_ST + bk * 136 + bc],     W + (size_t)(k0 + bk) * ND + colBase + bc);
        cp16(&Bsm[p * MMB_ST + bk * 136 + bc + 4], W + (size_t)(k0 + bk) * ND + colBase + bc + 4);
        cp_commit();
    }

    int stC = 0, stI = 2;
    for (int c = 0; c < 64; ++c) {
        if (c + 2 < 64) {
            int k0 = (c + 2) * 16;
            cp16(&Asm[stI * MMA_ST + ar * 20 + ac],     A + (size_t)(rowBase + ar) * ND + k0 + ac);
            cp16(&Asm[stI * MMA_ST + ar * 20 + ac + 4], A + (size_t)(rowBase + ar) * ND + k0 + ac + 4);
            cp16(&Bsm[stI * MMB_ST + bk * 136 + bc],     W + (size_t)(k0 + bk) * ND + colBase + bc);
            cp16(&Bsm[stI * MMB_ST + bk * 136 + bc + 4], W + (size_t)(k0 + bk) * ND + colBase + bc + 4);
            cp_commit();
            cp_wait2();
        } else if (c + 1 < 64) {
            cp_wait1();
        } else {
            cp_wait0();
        }
        __syncthreads();

        const float* Ast = &Asm[stC * MMA_ST];
        const float* Bst = &Bsm[stC * MMB_ST];
#pragma unroll
        for (int ks = 0; ks < 2; ++ks) {
            const int k = ks * 8;
            float a[2][4], b[8][2];
#pragma unroll
            for (int mt = 0; mt < 2; ++mt) {
                int m = warpM + mt * 16 + gm;
                a[mt][0] = f2tf(Ast[m * 20 + k + kq]);
                a[mt][1] = f2tf(Ast[(m + 8) * 20 + k + kq]);
                a[mt][2] = f2tf(Ast[m * 20 + k + kq + 4]);
                a[mt][3] = f2tf(Ast[(m + 8) * 20 + k + kq + 4]);
            }
#pragma unroll
            for (int nt = 0; nt < 8; ++nt) {
                int n = warpN + nt * 8 + gm;
                b[nt][0] = f2tf(Bst[(k + kq) * 136 + n]);
                b[nt][1] = f2tf(Bst[(k + kq + 4) * 136 + n]);
            }
#pragma unroll
            for (int mt = 0; mt < 2; ++mt)
#pragma unroll
                for (int nt = 0; nt < 8; ++nt)
                    mma_tf32(acc[mt][nt], a[mt], b[nt]);
        }
        __syncthreads();

        stC = (stC == 2) ? 0 : stC + 1;
        stI = (stI == 2) ? 0 : stI + 1;
    }

#pragma unroll
    for (int mt = 0; mt < 2; ++mt) {
#pragma unroll
        for (int nt = 0; nt < 8; ++nt) {
            int r0 = rowBase + warpM + mt * 16 + gm;
            int c0 = colBase + warpN + nt * 8 + kq * 2;
#pragma unroll
            for (int half = 0; half < 2; ++half) {
                int r = r0 + half * 8;
                float v0 = acc[mt][nt][half * 2 + 0] + bias[c0];
                float v1 = acc[mt][nt][half * 2 + 1] + bias[c0 + 1];
                if (splitR == 0) {
                    *(float2*)&C[(size_t)r * ND + c0] = make_float2(v0, v1);
                } else {
                    v0 = f2tf(v0); v1 = f2tf(v1);
                    int h = c0 >> 6, d = c0 & 63;
                    int bb = r / splitR, rr = r - bb * splitR;
                    *(float2*)&C[(((size_t)bb * NH + h) * splitR + rr) * HD + d] =
                        make_float2(v0, v1);
                }
            }
        }
    }
}

// ============================================================================
// nt64_pair_tf32: c2p and p2c; 4 batches per CTA sharing one pos tile.
// B (posk/posq) resident in 4 chunk stages; A streams through a 5-stage ring
// (chunk t -> stage t%5, chunk t+4 issued at iter t after the sync retiring
// chunk t-1's reads, which owns the same slot). wait_group 3 (tail 2/1/0).
// 512 MMAs/CTA, grid 1024. Dynamic smem 92160 B -> 2 CTAs/SM.
// ============================================================================
#define NTB_ST 2560   // 128*20 floats per stage
#define NT_SMEM ((5 * NTB_ST + 4 * NTB_ST) * 4)   // 92160 bytes

__global__ __launch_bounds__(256, 2) void nt64_pair_tf32(
    const float* __restrict__ q, const float* __restrict__ posk,
    const float* __restrict__ kk, const float* __restrict__ posq,
    __nv_bfloat16* __restrict__ c2p, __nv_bfloat16* __restrict__ p2c)
{
    extern __shared__ float sm[];
    float* Asm = sm;                  // 5-stage A ring
    float* Bsm = sm + 5 * NTB_ST;     // 4 resident B chunk stages

    const int t = threadIdx.x, l = t & 31, w = t >> 5;
    const int gm = l >> 2, kq = l & 3;
    const int warpM = (w >> 1) * 32, warpN = (w & 1) * 64;
    const int zz = blockIdx.z;
    const int kind = zz >> 4;          // 0: c2p(q,posk)  1: p2c(k,posq)
    const int g = zz & 15;             // pos tile index
    const int iBase = blockIdx.y * 128, jBase = blockIdx.x * 128;

    const float* Abase = kind ? kk : q;
    const float* Bb = (kind ? posq : posk) + (size_t)g * NK2 * HD;
    __nv_bfloat16* Cbase = kind ? p2c : c2p;

    const int sr = t >> 1, sc = (t & 1) * 8;

    // initial: 4 combined groups {B chunk c, A(batch0) chunk c}
    const float* Ab0 = Abase + (size_t)g * NS * HD;
#pragma unroll
    for (int c = 0; c < 4; ++c) {
        int d0 = c * 16;
        cp16(&Bsm[c * NTB_ST + sr * 20 + sc],     Bb + (size_t)(jBase + sr) * HD + d0 + sc);
        cp16(&Bsm[c * NTB_ST + sr * 20 + sc + 4], Bb + (size_t)(jBase + sr) * HD + d0 + sc + 4);
        cp16(&Asm[c * NTB_ST + sr * 20 + sc],     Ab0 + (size_t)(iBase + sr) * HD + d0 + sc);
        cp16(&Asm[c * NTB_ST + sr * 20 + sc + 4], Ab0 + (size_t)(iBase + sr) * HD + d0 + sc + 4);
        cp_commit();
    }

    const float sstore = 1.2247448713915890f;  // sqrt(1.5)

#pragma unroll
    for (int m = 0; m < 4; ++m) {
        float acc[2][8][4];
#pragma unroll
        for (int i = 0; i < 2; ++i)
#pragma unroll
            for (int j = 0; j < 8; ++j)
#pragma unroll
                for (int e = 0; e < 4; ++e) acc[i][j][e] = 0.f;

#pragma unroll
        for (int c = 0; c < 4; ++c) {
            const int tg = m * 4 + c;      // global chunk counter 0..15
            if (tg <= 12) cp_wait3();
            else if (tg == 13) cp_wait2();
            else if (tg == 14) cp_wait1();
            else cp_wait0();
            __syncthreads();

            // issue chunk tg+4 (batch (tg+4)/4, chunk (tg+4)%4) into stage (tg+4)%5
            if (tg + 4 < 16) {
                const int tn = tg + 4;
                const float* Abn = Abase + (size_t)(g + 16 * (tn >> 2)) * NS * HD;
                const int d0 = (tn & 3) * 16;
                float* st = &Asm[(tn % 5) * NTB_ST];
                cp16(&st[sr * 20 + sc],     Abn + (size_t)(iBase + sr) * HD + d0 + sc);
                cp16(&st[sr * 20 + sc + 4], Abn + (size_t)(iBase + sr) * HD + d0 + sc + 4);
                cp_commit();
            }

            const float* Ast = &Asm[(tg % 5) * NTB_ST];
            const float* Bst = &Bsm[c * NTB_ST];
#pragma unroll
            for (int ks = 0; ks < 2; ++ks) {
                const int k = ks * 8;
                float a[2][4], b[8][2];
#pragma unroll
                for (int mt = 0; mt < 2; ++mt) {
                    int mm = warpM + mt * 16 + gm;
                    a[mt][0] = Ast[mm * 20 + k + kq];
                    a[mt][1] = Ast[(mm + 8) * 20 + k + kq];
                    a[mt][2] = Ast[mm * 20 + k + kq + 4];
                    a[mt][3] = Ast[(mm + 8) * 20 + k + kq + 4];
                }
#pragma unroll
                for (int nt = 0; nt < 8; ++nt) {
                    int n = warpN + nt * 8 + gm;
                    b[nt][0] = Bst[n * 20 + k + kq];
                    b[nt][1] = Bst[n * 20 + k + kq + 4];
                }
#pragma unroll
                for (int mt = 0; mt < 2; ++mt)
#pragma unroll
                    for (int nt = 0; nt < 8; ++nt)
                        mma_tf32(acc[mt][nt], a[mt], b[nt]);
            }
        }

        // epilogue for batch m (overlaps next batch's in-flight loads)
        __nv_bfloat16* Cb = Cbase + (size_t)(g + 16 * m) * NS * NK2;
#pragma unroll
        for (int mt = 0; mt < 2; ++mt)
#pragma unroll
            for (int nt = 0; nt < 8; ++nt) {
                int r0 = iBase + warpM + mt * 16 + gm;
                int c0 = jBase + warpN + nt * 8 + kq * 2;
#pragma unroll
                for (int half = 0; half < 2; ++half) {
                    __nv_bfloat162 pk;
                    pk.x = __float2bfloat16(acc[mt][nt][half * 2 + 0] * sstore);
                    pk.y = __float2bfloat16(acc[mt][nt][half * 2 + 1] * sstore);
                    *(__nv_bfloat162*)&Cb[(size_t)(r0 + half * 8) * NK2 + c0] = pk;
                }
            }
    }
}

// ============================================================================
// flash_tf32: fused scores + online softmax + PV (round-15/16 64-row j-tiles,
// 2 CTAs/SM; unchanged)
// ============================================================================
#define FL_SMEM (2 * 64 * 72 * 4)

__global__ __launch_bounds__(256, 2) void flash_tf32(
    const float* __restrict__ q, const float* __restrict__ k,
    const float* __restrict__ v,
    const __nv_bfloat16* __restrict__ c2p, const __nv_bfloat16* __restrict__ p2c,
    const int2* __restrict__ idxt, float* __restrict__ ctx)
{
    extern __shared__ float smf[];
    float (*X0)[72] = (float(*)[72])smf;
    float (*X1)[72] = (float(*)[72])(smf + 64 * 72);

    const int t = threadIdx.x, l = t & 31, w = t >> 5;
    const int gm = l >> 2, kq = l & 3;
    const int warpM = w * 16;
    const int z = blockIdx.y;
    const int bz = z >> 4, h = z & 15;
    const int iBase = blockIdx.x * 128;

    const float* Qb = q + (size_t)z * NS * HD;
    const float* Kb = k + (size_t)z * NS * HD;
    const float* Vb = v + (size_t)z * NS * HD;
    const __nv_bfloat16* c2pr = c2p + (size_t)z * NS * NK2;
    const __nv_bfloat16* p2cr = p2c + (size_t)z * NS * NK2;

    const int sr = t >> 2, cb = (t & 3) * 16;
    const int i0 = iBase + warpM + gm;
    const int i1 = i0 + 8;

    // ---- load Q tile (128x64) through X0 in two halves, extract fragments ----
    float aq[8][4];
#pragma unroll
    for (int hv = 0; hv < 2; ++hv) {
#pragma unroll
        for (int i = 0; i < 4; ++i)
            cp16(&X0[sr][cb + i * 4],
                 Qb + (size_t)(iBase + hv * 64 + sr) * HD + cb + i * 4);
        cp_commit(); cp_wait0();
        __syncthreads();
        if ((warpM >> 6) == hv) {
            int m = (warpM & 63) + gm;
#pragma unroll
            for (int ks = 0; ks < 8; ++ks) {
                int kk = ks * 8;
                aq[ks][0] = X0[m][kk + kq];
                aq[ks][1] = X0[m + 8][kk + kq];
                aq[ks][2] = X0[m][kk + kq + 4];
                aq[ks][3] = X0[m + 8][kk + kq + 4];
            }
        }
        __syncthreads();
    }

    // prefetch K(0) -> X0
#pragma unroll
    for (int i = 0; i < 4; ++i)
        cp16(&X0[sr][cb + i * 4], Kb + (size_t)sr * HD + cb + i * 4);
    cp_commit();   // pending: [K0]

    float m0 = -INFINITY, m1 = -INFINITY, l0 = 0.f, l1 = 0.f;   // raw units
    float o[8][4];
#pragma unroll
    for (int i = 0; i < 8; ++i)
#pragma unroll
        for (int e = 0; e < 4; ++e) o[i][e] = 0.f;

    const float inv192 = 0.07216878364870322f;  // 1/sqrt(64*3)
    const int srcA = (l & ~3) | (kq >> 1);
    const int srcB = srcA + 2;
    const bool odd = (kq & 1);

    for (int jt = 0; jt < 16; ++jt) {
        const int jBase = jt * 64;

        // issue V(jt) -> X1
#pragma unroll
        for (int i = 0; i < 4; ++i)
            cp16(&X1[sr][cb + i * 4], Vb + (size_t)(jBase + sr) * HD + cb + i * 4);
        cp_commit();        // pending: [K(jt), V(jt)]

        // ---- bias gathers initialize S (overlap with K(jt) in flight) ----
        float sc[8][4];
#pragma unroll
        for (int nt = 0; nt < 8; ++nt) {
#pragma unroll
            for (int e = 0; e < 4; ++e) {
                int i = (e < 2) ? i0 : i1;
                int j = jBase + nt * 8 + kq * 2 + (e & 1);
                int2 ip = idxt[i - j + (NS - 1)];
                sc[nt][e] = __bfloat162float(c2pr[(size_t)i * NK2 + ip.x])
                          + __bfloat162float(p2cr[(size_t)j * NK2 + ip.y]);
            }
        }

        cp_wait1();         // K(jt) resident
        __syncthreads();

        // ---- S += Q K^T (64 MMAs) ----
#pragma unroll
        for (int ks = 0; ks < 8; ++ks) {
            const int kk = ks * 8;
#pragma unroll
            for (int nt = 0; nt < 8; ++nt) {
                int n = nt * 8 + gm;
                float b[2];
                b[0] = X0[n][kk + kq];
                b[1] = X0[n][kk + kq + 4];
                mma_tf32(sc[nt], aq[ks], b);
            }
        }
        __syncthreads();

        // prefetch K(jt+1) -> X0 (overlaps softmax)
        if (jt + 1 < 16) {
#pragma unroll
            for (int i = 0; i < 4; ++i)
                cp16(&X0[sr][cb + i * 4],
                     Kb + (size_t)((jt + 1) * 64 + sr) * HD + cb + i * 4);
            cp_commit();
        }

        // ---- online softmax ----
        float tm0 = -INFINITY, tm1 = -INFINITY;
#pragma unroll
        for (int nt = 0; nt < 8; ++nt) {
            tm0 = fmaxf(tm0, fmaxf(sc[nt][0], sc[nt][1]));
            tm1 = fmaxf(tm1, fmaxf(sc[nt][2], sc[nt][3]));
        }
        tm0 = fmaxf(tm0, __shfl_xor_sync(0xffffffffu, tm0, 1));
        tm0 = fmaxf(tm0, __shfl_xor_sync(0xffffffffu, tm0, 2));
        tm1 = fmaxf(tm1, __shfl_xor_sync(0xffffffffu, tm1, 1));
        tm1 = fmaxf(tm1, __shfl_xor_sync(0xffffffffu, tm1, 2));

        float mn0 = fmaxf(m0, tm0), mn1 = fmaxf(m1, tm1);
        float fac0 = __expf((m0 - mn0) * inv192);
        float fac1 = __expf((m1 - mn1) * inv192);
        m0 = mn0; m1 = mn1;

        float s0 = 0.f, s1 = 0.f;
#pragma unroll
        for (int nt = 0; nt < 8; ++nt) {
            sc[nt][0] = f2tf(__expf((sc[nt][0] - mn0) * inv192));
            sc[nt][1] = f2tf(__expf((sc[nt][1] - mn0) * inv192));
            sc[nt][2] = f2tf(__expf((sc[nt][2] - mn1) * inv192));
            sc[nt][3] = f2tf(__expf((sc[nt][3] - mn1) * inv192));
            s0 += sc[nt][0] + sc[nt][1];
            s1 += sc[nt][2] + sc[nt][3];
        }
        s0 += __shfl_xor_sync(0xffffffffu, s0, 1);
        s0 += __shfl_xor_sync(0xffffffffu, s0, 2);
        s1 += __shfl_xor_sync(0xffffffffu, s1, 1);
        s1 += __shfl_xor_sync(0xffffffffu, s1, 2);
        l0 = l0 * fac0 + s0;
        l1 = l1 * fac1 + s1;

#pragma unroll
        for (int nt = 0; nt < 8; ++nt) {
            o[nt][0] *= fac0; o[nt][1] *= fac0;
            o[nt][2] *= fac1; o[nt][3] *= fac1;
        }

        // ---- wait V(jt), then PV (64 MMAs) ----
        if (jt + 1 < 16) cp_wait1(); else cp_wait0();
        __syncthreads();

#pragma unroll
        for (int ksg = 0; ksg < 8; ++ksg) {
            float e0 = __shfl_sync(0xffffffffu, sc[ksg][0], srcA);
            float e1 = __shfl_sync(0xffffffffu, sc[ksg][1], srcA);
            float e2 = __shfl_sync(0xffffffffu, sc[ksg][2], srcA);
            float e3 = __shfl_sync(0xffffffffu, sc[ksg][3], srcA);
            float f0 = __shfl_sync(0xffffffffu, sc[ksg][0], srcB);
            float f1 = __shfl_sync(0xffffffffu, sc[ksg][1], srcB);
            float f2 = __shfl_sync(0xffffffffu, sc[ksg][2], srcB);
            float f3 = __shfl_sync(0xffffffffu, sc[ksg][3], srcB);
            float pa[4];
            pa[0] = odd ? e1 : e0;
            pa[1] = odd ? e3 : e2;
            pa[2] = odd ? f1 : f0;
            pa[3] = odd ? f3 : f2;
#pragma unroll
            for (int nt = 0; nt < 8; ++nt) {
                int n = nt * 8 + gm;
                float b[2];
                b[0] = X1[ksg * 8 + kq][n];
                b[1] = X1[ksg * 8 + kq + 4][n];
                mma_tf32(o[nt], pa, b);
            }
        }
        __syncthreads();
    }

    // ---- normalize and store ctx ----
    float r0 = 1.0f / l0, r1 = 1.0f / l1;
#pragma unroll
    for (int nt = 0; nt < 8; ++nt) {
        int c0 = nt * 8 + kq * 2;
        *(float2*)&ctx[((size_t)bz * NS + i0) * ND + h * HD + c0] =
            make_float2(o[nt][0] * r0, o[nt][1] * r0);
        *(float2*)&ctx[((size_t)bz * NS + i1) * ND + h * HD + c0] =
            make_float2(o[nt][2] * r1, o[nt][3] * r1);
    }
}

// ---------------- launch ----------------
extern "C" void kernel_launch(void* const* d_in, const int* in_sizes, int n_in,
                              void* d_out, int out_size) {
    const float* hs    = (const float*)d_in[0];
    const float* Wq    = (const float*)d_in[1];
    const float* bq    = (const float*)d_in[2];
    const float* Wk    = (const float*)d_in[3];
    const float* bk    = (const float*)d_in[4];
    const float* Wv    = (const float*)d_in[5];
    const float* bv    = (const float*)d_in[6];
    const float* Wo    = (const float*)d_in[7];
    const float* bo    = (const float*)d_in[8];
    const float* rel   = (const float*)d_in[9];
    const float* ln_g  = (const float*)d_in[10];
    const float* ln_b  = (const float*)d_in[11];
    const float* Wpk   = (const float*)d_in[12];
    const float* bpk   = (const float*)d_in[13];
    const float* Wpq   = (const float*)d_in[14];
    const float* bpq   = (const float*)d_in[15];
    float* out = (float*)d_out;

    float *p_re, *p_q, *p_k, *p_v, *p_posk, *p_posq, *p_ctx;
    __nv_bfloat16 *p_c2p, *p_p2c;
    int2* p_idx;
    cudaGetSymbolAddress((void**)&p_re, g_re);
    cudaGetSymbolAddress((void**)&p_q, g_q);
    cudaGetSymbolAddress((void**)&p_k, g_k);
    cudaGetSymbolAddress((void**)&p_v, g_v);
    cudaGetSymbolAddress((void**)&p_posk, g_posk);
    cudaGetSymbolAddress((void**)&p_posq, g_posq);
    cudaGetSymbolAddress((void**)&p_c2p, g_c2p);
    cudaGetSymbolAddress((void**)&p_p2c, g_p2c);
    cudaGetSymbolAddress((void**)&p_ctx, g_ctx);
    cudaGetSymbolAddress((void**)&p_idx, g_idx);

    static bool attr_done = false;
    if (!attr_done) {
        cudaFuncSetAttribute(flash_tf32,
                             cudaFuncAttributeMaxDynamicSharedMemorySize, FL_SMEM);
        cudaFuncSetAttribute(mm_jobs_tf32,
                             cudaFuncAttributeMaxDynamicSharedMemorySize, MM_SMEM);
        cudaFuncSetAttribute(nt64_pair_tf32,
                             cudaFuncAttributeMaxDynamicSharedMemorySize, NT_SMEM);
        attr_done = true;
    }

    build_idx_kernel<<<9, 256>>>(p_idx);
    ln_kernel<<<NK2, 256>>>(rel, ln_g, ln_b, p_re);

    // merged Q/K/V + pos-k/pos-q projections in one launch
    MMJobs jobs;
    jobs.j[0] = { hs,   Wq,  bq,  p_q,    NB * NS, NS  };
    jobs.j[1] = { hs,   Wk,  bk,  p_k,    NB * NS, NS  };
    jobs.j[2] = { hs,   Wv,  bv,  p_v,    NB * NS, NS  };
    jobs.j[3] = { p_re, Wpk, bpk, p_posk, NK2,     NK2 };
    jobs.j[4] = { p_re, Wpq, bpq, p_posq, NK2,     NK2 };
    mm_jobs_tf32<<<dim3(8, 32, 5), 256, MM_SMEM>>>(jobs);

    // c2p and p2c: 4 batches per CTA sharing one pos tile
    nt64_pair_tf32<<<dim3(4, 8, 32), 256, NT_SMEM>>>(p_q, p_posk, p_k, p_posq, p_c2p, p_p2c);

    // fused attention (2 CTAs/SM)
    flash_tf32<<<dim3(8, 64), 256, FL_SMEM>>>(p_q, p_k, p_v, p_c2p, p_p2c, p_idx, p_ctx);

    // out = ctx @ Wo + bo
    MMJobs jo;
    jo.j[0] = { p_ctx, Wo, bo, out, NB * NS, 0 };
    jo.j[1] = jo.j[0]; jo.j[2] = jo.j[0]; jo.j[3] = jo.j[0]; jo.j[4] = jo.j[0];
    mm_jobs_tf32<<<dim3(8, 32, 1), 256, MM_SMEM>>>(jo);
}